// round 5
// baseline (speedup 1.0000x reference)
#include <cuda_runtime.h>
#include <cstdint>
#include <cstddef>

// ---------------------------------------------------------------------------
// GraphSAGE 2-layer, GB300 sm_103a.
//   h1 = relu( segmean(x@W1l) + b1 + x@W1r )
//   out =      segmean(h1@W2l) + b2 + h1@W2r
// GEMMs fused as [K,256] = [W_l | W_r]; aggregation done in projected (128-d)
// space (linearity of mean), 3x less edge traffic than feature-space agg.
// GEMM via tf32 mma.sync.m16n8k8 (fp32 accum) for <=1e-3 rel err.
// ---------------------------------------------------------------------------

#define MAXN 100000
#define MAXE 200000

// scratch (static device globals: allocation-free contract)
__device__ float g_W1[384 * 256];
__device__ float g_W2[128 * 256];
__device__ float g_lin[(size_t)MAXN * 256];   // x@[W_l|W_r] then h1@[W_l|W_r]
__device__ float g_agg[(size_t)MAXN * 128];   // edge-aggregated first half
__device__ float g_h1 [(size_t)MAXN * 128];
__device__ float g_cnt[MAXN];
__device__ int   g_src[MAXE];
__device__ int   g_dst[MAXE];
__device__ int   g_is64;

__device__ __forceinline__ unsigned f2tf(float x) {
    unsigned r;
    asm("cvt.rna.tf32.f32 %0, %1;" : "=r"(r) : "f"(x));
    return r;
}

// ---------------- edge dtype detect + normalize ----------------------------
__global__ void detect_k(const unsigned* __restrict__ w) {
    // int64 edges (values < 2^31, nonneg) => every high word of first 64
    // entries is 0. int32 edges: odd words are random node ids; P(all 0)=~0.
    int is64 = 1;
    for (int i = 0; i < 64; i++)
        if (w[2 * i + 1] != 0u) { is64 = 0; break; }
    g_is64 = is64;
}

__global__ void cvt_edges_k(const void* __restrict__ ei, int E) {
    int i = blockIdx.x * blockDim.x + threadIdx.x;
    if (i >= E) return;
    if (g_is64) {
        const long long* p = (const long long*)ei;
        g_src[i] = (int)p[i];
        g_dst[i] = (int)p[E + i];
    } else {
        const int* p = (const int*)ei;
        g_src[i] = p[i];
        g_dst[i] = p[E + i];
    }
}

// ---------------- small utility kernels ------------------------------------
__global__ void zero_k(float4* __restrict__ p, int n4) {
    int i = blockIdx.x * blockDim.x + threadIdx.x;
    if (i < n4) p[i] = make_float4(0.f, 0.f, 0.f, 0.f);
}

__global__ void pack_w_k(const float* __restrict__ Wl, const float* __restrict__ Wr,
                         float* __restrict__ Wc, int K) {
    int idx = blockIdx.x * blockDim.x + threadIdx.x;
    if (idx >= K * 256) return;
    int k = idx >> 8, n = idx & 255;
    float v = (n < 128) ? Wl[k * 128 + n] : Wr[k * 128 + n - 128];
    Wc[idx] = __uint_as_float(f2tf(v));   // pre-round weights to tf32
}

__global__ void count_k(float* __restrict__ cnt, int E) {
    int e = blockIdx.x * blockDim.x + threadIdx.x;
    if (e < E) atomicAdd(cnt + g_dst[e], 1.0f);
}

// one warp per edge: gather 128 floats of lin[src], atomic-add into agg[dst]
__global__ void scatter_k(const float* __restrict__ lin, float* __restrict__ agg, int E) {
    int gt = blockIdx.x * blockDim.x + threadIdx.x;
    int e = gt >> 5, lane = gt & 31;
    if (e >= E) return;
    int s = g_src[e];
    int d = g_dst[e];
    float4 v = *(const float4*)(lin + (size_t)s * 256 + lane * 4);
    float* b = agg + (size_t)d * 128 + lane * 4;
    atomicAdd(b + 0, v.x);
    atomicAdd(b + 1, v.y);
    atomicAdd(b + 2, v.z);
    atomicAdd(b + 3, v.w);
}

__global__ void epilogue_k(const float* __restrict__ lin, const float* __restrict__ agg,
                           const float* __restrict__ cnt, const float* __restrict__ bias,
                           float* __restrict__ out, int M, int do_relu) {
    int gt = blockIdx.x * blockDim.x + threadIdx.x;
    int node = gt >> 5, lane = gt & 31;
    if (node >= M) return;
    float inv = 1.0f / fmaxf(cnt[node], 1.0f);
    float4 a = *(const float4*)(agg + (size_t)node * 128 + lane * 4);
    float4 r = *(const float4*)(lin + (size_t)node * 256 + 128 + lane * 4);
    float4 b = *(const float4*)(bias + lane * 4);
    float4 o;
    o.x = fmaf(a.x, inv, b.x) + r.x;
    o.y = fmaf(a.y, inv, b.y) + r.y;
    o.z = fmaf(a.z, inv, b.z) + r.z;
    o.w = fmaf(a.w, inv, b.w) + r.w;
    if (do_relu) {
        o.x = fmaxf(o.x, 0.f); o.y = fmaxf(o.y, 0.f);
        o.z = fmaxf(o.z, 0.f); o.w = fmaxf(o.w, 0.f);
    }
    *(float4*)(out + (size_t)node * 128 + lane * 4) = o;
}

// ---------------- tf32 GEMM: C[M,256] = A[M,K] @ W[K,256] ------------------
// block tile 128x128, BK=16, 8 warps (4x2), warp tile 32x64,
// mma.sync.m16n8k8 tf32, double-buffered smem, reg-staged gmem loads.
__global__ __launch_bounds__(256, 2) void gemm_tf32_k(
    const float* __restrict__ A, const float* __restrict__ W,
    float* __restrict__ C, int M, int K)
{
    __shared__ __align__(16) float As[2][128][20];   // +4 pad: conflict-free frags
    __shared__ __align__(16) float Bs[2][16][136];   // +8 pad: conflict-free frags

    const int tid = threadIdx.x;
    const int warp = tid >> 5, lane = tid & 31;
    const int wm = warp >> 1, wn = warp & 1;      // 4 x 2 warp grid
    const int g = lane >> 2, tg = lane & 3;
    const int rowBlock = blockIdx.x * 128;
    const int colBlock = blockIdx.y * 128;

    float acc[2][8][4];
#pragma unroll
    for (int i = 0; i < 2; i++)
#pragma unroll
        for (int j = 0; j < 8; j++)
#pragma unroll
            for (int k = 0; k < 4; k++) acc[i][j][k] = 0.f;

    const int NT = K >> 4;

    // prologue: tile 0 -> smem buf 0
    {
#pragma unroll
        for (int i = 0; i < 2; i++) {
            int u = tid + i * 256;           // 512 float4 units for A (128 rows x 4)
            int row = u >> 2, q = u & 3;
            int gr = rowBlock + row;
            float4 v = make_float4(0.f, 0.f, 0.f, 0.f);
            if (gr < M) v = *(const float4*)(A + (size_t)gr * K + q * 4);
            *(float4*)(&As[0][row][q * 4]) = v;
        }
#pragma unroll
        for (int i = 0; i < 2; i++) {
            int u = tid + i * 256;           // 512 float4 units for B (16 rows x 32)
            int r = u >> 5, q = u & 31;
            float4 v = *(const float4*)(W + (size_t)r * 256 + colBlock + q * 4);
            *(float4*)(&Bs[0][r][q * 4]) = v;
        }
    }
    __syncthreads();

    float4 ra[2], rb[2];
    for (int kt = 0; kt < NT; kt++) {
        const int cur = kt & 1;
        if (kt + 1 < NT) {
            const int k0 = (kt + 1) << 4;
#pragma unroll
            for (int i = 0; i < 2; i++) {
                int u = tid + i * 256;
                int row = u >> 2, q = u & 3;
                int gr = rowBlock + row;
                ra[i] = make_float4(0.f, 0.f, 0.f, 0.f);
                if (gr < M) ra[i] = *(const float4*)(A + (size_t)gr * K + k0 + q * 4);
            }
#pragma unroll
            for (int i = 0; i < 2; i++) {
                int u = tid + i * 256;
                int r = u >> 5, q = u & 31;
                rb[i] = *(const float4*)(W + (size_t)(k0 + r) * 256 + colBlock + q * 4);
            }
        }

#pragma unroll
        for (int ks = 0; ks < 2; ks++) {
            const int kk = ks * 8;
            unsigned a[2][4];
#pragma unroll
            for (int mt = 0; mt < 2; mt++) {
                int r = wm * 32 + mt * 16;
                a[mt][0] = f2tf(As[cur][r + g    ][kk + tg    ]);
                a[mt][1] = f2tf(As[cur][r + g + 8][kk + tg    ]);
                a[mt][2] = f2tf(As[cur][r + g    ][kk + tg + 4]);
                a[mt][3] = f2tf(As[cur][r + g + 8][kk + tg + 4]);
            }
            unsigned b[8][2];
#pragma unroll
            for (int nt = 0; nt < 8; nt++) {
                int c = wn * 64 + nt * 8 + g;
                b[nt][0] = __float_as_uint(Bs[cur][kk + tg    ][c]);
                b[nt][1] = __float_as_uint(Bs[cur][kk + tg + 4][c]);
            }
#pragma unroll
            for (int mt = 0; mt < 2; mt++)
#pragma unroll
                for (int nt = 0; nt < 8; nt++) {
                    asm volatile(
                        "mma.sync.aligned.m16n8k8.row.col.f32.tf32.tf32.f32 "
                        "{%0,%1,%2,%3}, {%4,%5,%6,%7}, {%8,%9}, {%0,%1,%2,%3};\n"
                        : "+f"(acc[mt][nt][0]), "+f"(acc[mt][nt][1]),
                          "+f"(acc[mt][nt][2]), "+f"(acc[mt][nt][3])
                        : "r"(a[mt][0]), "r"(a[mt][1]), "r"(a[mt][2]), "r"(a[mt][3]),
                          "r"(b[nt][0]), "r"(b[nt][1]));
                }
        }
        __syncthreads();
        if (kt + 1 < NT) {
            const int nb = cur ^ 1;
#pragma unroll
            for (int i = 0; i < 2; i++) {
                int u = tid + i * 256;
                int row = u >> 2, q = u & 3;
                *(float4*)(&As[nb][row][q * 4]) = ra[i];
            }
#pragma unroll
            for (int i = 0; i < 2; i++) {
                int u = tid + i * 256;
                int r = u >> 5, q = u & 31;
                *(float4*)(&Bs[nb][r][q * 4]) = rb[i];
            }
            __syncthreads();
        }
    }

    // epilogue
#pragma unroll
    for (int mt = 0; mt < 2; mt++)
#pragma unroll
        for (int nt = 0; nt < 8; nt++) {
            int row0 = rowBlock + wm * 32 + mt * 16 + g;
            int col  = colBlock + wn * 64 + nt * 8 + tg * 2;
            if (row0 < M)
                *(float2*)(C + (size_t)row0 * 256 + col) =
                    make_float2(acc[mt][nt][0], acc[mt][nt][1]);
            int row1 = row0 + 8;
            if (row1 < M)
                *(float2*)(C + (size_t)row1 * 256 + col) =
                    make_float2(acc[mt][nt][2], acc[mt][nt][3]);
        }
}

// ---------------------------------------------------------------------------
extern "C" void kernel_launch(void* const* d_in, const int* in_sizes, int n_in,
                              void* d_out, int out_size) {
    const float* x   = (const float*)d_in[0];
    const void*  ei  = d_in[1];
    const float* W1l = (const float*)d_in[2];
    const float* b1  = (const float*)d_in[3];
    const float* W1r = (const float*)d_in[4];
    const float* W2l = (const float*)d_in[5];
    const float* b2  = (const float*)d_in[6];
    const float* W2r = (const float*)d_in[7];
    float* out = (float*)d_out;

    const int M = in_sizes[0] / 384;
    const int E = in_sizes[1] / 2;

    float *pW1, *pW2, *pLin, *pAgg, *pH1, *pCnt;
    cudaGetSymbolAddress((void**)&pW1, g_W1);
    cudaGetSymbolAddress((void**)&pW2, g_W2);
    cudaGetSymbolAddress((void**)&pLin, g_lin);
    cudaGetSymbolAddress((void**)&pAgg, g_agg);
    cudaGetSymbolAddress((void**)&pH1, g_h1);
    cudaGetSymbolAddress((void**)&pCnt, g_cnt);

    const int T = 256;
    // edge normalize + degree counts + weight packing (independent setup)
    detect_k<<<1, 1>>>((const unsigned*)ei);
    cvt_edges_k<<<(E + T - 1) / T, T>>>(ei, E);
    zero_k<<<(M / 4 + T - 1) / T, T>>>((float4*)pCnt, M / 4);
    count_k<<<(E + T - 1) / T, T>>>(pCnt, E);
    pack_w_k<<<(384 * 256 + T - 1) / T, T>>>(W1l, W1r, pW1, 384);
    pack_w_k<<<(128 * 256 + T - 1) / T, T>>>(W2l, W2r, pW2, 128);

    dim3 gg((M + 127) / 128, 2);
    const int n4agg = M * 32;           // M*128/4 float4s

    // ---- layer 1 ----
    gemm_tf32_k<<<gg, T>>>(x, pW1, pLin, M, 384);
    zero_k<<<(n4agg + T - 1) / T, T>>>((float4*)pAgg, n4agg);
    scatter_k<<<(E * 32 + T - 1) / T, T>>>(pLin, pAgg, E);
    epilogue_k<<<(M * 32 + T - 1) / T, T>>>(pLin, pAgg, pCnt, b1, pH1, M, 1);

    // ---- layer 2 ----
    gemm_tf32_k<<<gg, T>>>(pH1, pW2, pLin, M, 128);
    zero_k<<<(n4agg + T - 1) / T, T>>>((float4*)pAgg, n4agg);
    scatter_k<<<(E * 32 + T - 1) / T, T>>>(pLin, pAgg, E);
    epilogue_k<<<(M * 32 + T - 1) / T, T>>>(pLin, pAgg, pCnt, b2, out, M, 0);
}

// round 9
// speedup vs baseline: 1.0216x; 1.0216x over previous
#include <cuda_runtime.h>
#include <cuda_bf16.h>
#include <cstdint>
#include <cstddef>

// ---------------------------------------------------------------------------
// GraphSAGE 2-layer, GB300 sm_103a (base-PTX target: no tcgen05 available).
//   h1 = relu( segmean(x@W1l) + b1 + x@W1r )
//   out =      segmean(h1@W2l) + b2 + h1@W2r
// GEMMs fused as [K,256] = [W_l | W_r]; aggregation in projected 128-d space
// (linearity of mean): 3x less edge traffic than feature-space aggregation.
// GEMM: tf32 mma.sync.m16n8k8 (fp32 accum), A pre-rounded to tf32 at staging,
// A fragments via ldmatrix.x4, grid ordered for A L2 reuse.
// ---------------------------------------------------------------------------

#define MAXN 100000
#define MAXE 200000

// scratch (static device globals: allocation-free contract)
__device__ float g_W1[384 * 256];
__device__ float g_W2[128 * 256];
__device__ float g_lin[(size_t)MAXN * 256];
__device__ float g_agg[(size_t)MAXN * 128];
__device__ float g_h1 [(size_t)MAXN * 128];
__device__ float g_cnt[MAXN];
__device__ int   g_src[MAXE];
__device__ int   g_dst[MAXE];
__device__ int   g_is64;

__device__ __forceinline__ unsigned f2tf(float x) {
    unsigned r;
    asm("cvt.rna.tf32.f32 %0, %1;" : "=r"(r) : "f"(x));
    return r;
}

__device__ __forceinline__ uint32_t smem_u32(const void* p) {
    uint32_t a;
    asm("{ .reg .u64 t; cvta.to.shared.u64 t, %1; cvt.u32.u64 %0, t; }"
        : "=r"(a) : "l"(p));
    return a;
}

// ---------------- edge dtype detect + normalize + degree -------------------
__global__ void detect_k(const unsigned* __restrict__ w) {
    // int64 edges (nonneg, < 2^31) => all high words of first 64 entries are 0.
    int is64 = 1;
    for (int i = 0; i < 64; i++)
        if (w[2 * i + 1] != 0u) { is64 = 0; break; }
    g_is64 = is64;
}

__global__ void prep_edges_k(const void* __restrict__ ei, float* __restrict__ cnt, int E) {
    int i = blockIdx.x * blockDim.x + threadIdx.x;
    if (i >= E) return;
    int s, d;
    if (g_is64) {
        const long long* p = (const long long*)ei;
        s = (int)p[i];
        d = (int)p[E + i];
    } else {
        const int* p = (const int*)ei;
        s = p[i];
        d = p[E + i];
    }
    g_src[i] = s;
    g_dst[i] = d;
    atomicAdd(cnt + d, 1.0f);
}

// ---------------- weight pack: [K,128]x2 -> [K,256], tf32 pre-rounded ------
__global__ void pack_w_k(const float* __restrict__ Wl, const float* __restrict__ Wr,
                         float* __restrict__ Wc, int K) {
    int idx = blockIdx.x * blockDim.x + threadIdx.x;
    if (idx >= K * 256) return;
    int k = idx >> 8, n = idx & 255;
    float v = (n < 128) ? Wl[k * 128 + n] : Wr[k * 128 + n - 128];
    Wc[idx] = __uint_as_float(f2tf(v));
}

// one warp per edge: gather 128 floats of lin[src], atomic-add into agg[dst]
__global__ void scatter_k(const float* __restrict__ lin, float* __restrict__ agg, int E) {
    int gt = blockIdx.x * blockDim.x + threadIdx.x;
    int e = gt >> 5, lane = gt & 31;
    if (e >= E) return;
    int s = g_src[e];
    int d = g_dst[e];
    float4 v = *(const float4*)(lin + (size_t)s * 256 + lane * 4);
    float* b = agg + (size_t)d * 128 + lane * 4;
    atomicAdd(b + 0, v.x);
    atomicAdd(b + 1, v.y);
    atomicAdd(b + 2, v.z);
    atomicAdd(b + 3, v.w);
}

__global__ void epilogue_k(const float* __restrict__ lin, const float* __restrict__ agg,
                           const float* __restrict__ cnt, const float* __restrict__ bias,
                           float* __restrict__ out, int M, int do_relu) {
    int gt = blockIdx.x * blockDim.x + threadIdx.x;
    int node = gt >> 5, lane = gt & 31;
    if (node >= M) return;
    float inv = 1.0f / fmaxf(cnt[node], 1.0f);
    float4 a = *(const float4*)(agg + (size_t)node * 128 + lane * 4);
    float4 r = *(const float4*)(lin + (size_t)node * 256 + 128 + lane * 4);
    float4 b = *(const float4*)(bias + lane * 4);
    float4 o;
    o.x = fmaf(a.x, inv, b.x) + r.x;
    o.y = fmaf(a.y, inv, b.y) + r.y;
    o.z = fmaf(a.z, inv, b.z) + r.z;
    o.w = fmaf(a.w, inv, b.w) + r.w;
    if (do_relu) {
        o.x = fmaxf(o.x, 0.f); o.y = fmaxf(o.y, 0.f);
        o.z = fmaxf(o.z, 0.f); o.w = fmaxf(o.w, 0.f);
    }
    *(float4*)(out + (size_t)node * 128 + lane * 4) = o;
}

// ---------------- tf32 GEMM: C[M,256] = A[M,K] @ W[K,256] ------------------
// block tile 128x128, BK=16, 8 warps (4x2), warp tile 32x64,
// mma.sync.m16n8k8 tf32, double-buffered smem, reg-staged gmem loads.
// A rounded to tf32 at staging; A fragments loaded via ldmatrix.x4.
// grid = (2 colblocks, rowblocks): both colblocks of a row are wave-adjacent
// so the second read of the A tile hits L2.
__global__ __launch_bounds__(256, 2) void gemm_tf32_k(
    const float* __restrict__ A, const float* __restrict__ W,
    float* __restrict__ C, int M, int K)
{
    __shared__ __align__(16) float As[2][128][20];   // +4 pad
    __shared__ __align__(16) float Bs[2][16][136];   // +8 pad

    const int tid = threadIdx.x;
    const int warp = tid >> 5, lane = tid & 31;
    const int wm = warp >> 1, wn = warp & 1;      // 4 x 2 warp grid
    const int g = lane >> 2, tg = lane & 3;
    const int colBlock = blockIdx.x * 128;
    const int rowBlock = blockIdx.y * 128;

    float acc[2][8][4];
#pragma unroll
    for (int i = 0; i < 2; i++)
#pragma unroll
        for (int j = 0; j < 8; j++)
#pragma unroll
            for (int k = 0; k < 4; k++) acc[i][j][k] = 0.f;

    const int NT = K >> 4;

    // per-thread ldmatrix source addresses (A fragments, m8n8.x4 over b16):
    // lane L supplies row r0 + (L&15), 16B column group (L>>4).
    const uint32_t asbase0 = smem_u32(&As[0][0][0]);
    const uint32_t asbase1 = smem_u32(&As[1][0][0]);
    const uint32_t aoff0 = ((wm * 32 + (lane & 15)) * 20 + ((lane >> 4) * 4)) * 4;
    const uint32_t aoff1 = aoff0 + 16 * 20 * 4;

    // prologue: tile 0 -> smem buf 0 (A rounded to tf32 here)
    {
#pragma unroll
        for (int i = 0; i < 2; i++) {
            int u = tid + i * 256;
            int row = u >> 2, q = u & 3;
            int gr = rowBlock + row;
            float4 v = make_float4(0.f, 0.f, 0.f, 0.f);
            if (gr < M) v = *(const float4*)(A + (size_t)gr * K + q * 4);
            v.x = __uint_as_float(f2tf(v.x)); v.y = __uint_as_float(f2tf(v.y));
            v.z = __uint_as_float(f2tf(v.z)); v.w = __uint_as_float(f2tf(v.w));
            *(float4*)(&As[0][row][q * 4]) = v;
        }
#pragma unroll
        for (int i = 0; i < 2; i++) {
            int u = tid + i * 256;
            int r = u >> 5, q = u & 31;
            float4 v = *(const float4*)(W + (size_t)r * 256 + colBlock + q * 4);
            *(float4*)(&Bs[0][r][q * 4]) = v;
        }
    }
    __syncthreads();

    float4 ra[2], rb[2];
    for (int kt = 0; kt < NT; kt++) {
        const int cur = kt & 1;
        if (kt + 1 < NT) {
            const int k0 = (kt + 1) << 4;
#pragma unroll
            for (int i = 0; i < 2; i++) {
                int u = tid + i * 256;
                int row = u >> 2, q = u & 3;
                int gr = rowBlock + row;
                ra[i] = make_float4(0.f, 0.f, 0.f, 0.f);
                if (gr < M) ra[i] = *(const float4*)(A + (size_t)gr * K + k0 + q * 4);
            }
#pragma unroll
            for (int i = 0; i < 2; i++) {
                int u = tid + i * 256;
                int r = u >> 5, q = u & 31;
                rb[i] = *(const float4*)(W + (size_t)(k0 + r) * 256 + colBlock + q * 4);
            }
        }

        const uint32_t abase = (cur ? asbase1 : asbase0);
#pragma unroll
        for (int ks = 0; ks < 2; ks++) {
            const int kk = ks * 8;
            unsigned a[2][4];
#pragma unroll
            for (int mt = 0; mt < 2; mt++) {
                uint32_t addr = abase + (mt ? aoff1 : aoff0) + ks * 32;
                asm volatile(
                    "ldmatrix.sync.aligned.m8n8.x4.shared.b16 {%0,%1,%2,%3}, [%4];"
                    : "=r"(a[mt][0]), "=r"(a[mt][1]), "=r"(a[mt][2]), "=r"(a[mt][3])
                    : "r"(addr));
            }
            unsigned b[8][2];
#pragma unroll
            for (int nt = 0; nt < 8; nt++) {
                int c = wn * 64 + nt * 8 + g;
                b[nt][0] = __float_as_uint(Bs[cur][kk + tg    ][c]);
                b[nt][1] = __float_as_uint(Bs[cur][kk + tg + 4][c]);
            }
#pragma unroll
            for (int mt = 0; mt < 2; mt++)
#pragma unroll
                for (int nt = 0; nt < 8; nt++) {
                    asm volatile(
                        "mma.sync.aligned.m16n8k8.row.col.f32.tf32.tf32.f32 "
                        "{%0,%1,%2,%3}, {%4,%5,%6,%7}, {%8,%9}, {%0,%1,%2,%3};\n"
                        : "+f"(acc[mt][nt][0]), "+f"(acc[mt][nt][1]),
                          "+f"(acc[mt][nt][2]), "+f"(acc[mt][nt][3])
                        : "r"(a[mt][0]), "r"(a[mt][1]), "r"(a[mt][2]), "r"(a[mt][3]),
                          "r"(b[nt][0]), "r"(b[nt][1]));
                }
        }
        __syncthreads();
        if (kt + 1 < NT) {
            const int nb = cur ^ 1;
#pragma unroll
            for (int i = 0; i < 2; i++) {
                int u = tid + i * 256;
                int row = u >> 2, q = u & 3;
                float4 v = ra[i];
                v.x = __uint_as_float(f2tf(v.x)); v.y = __uint_as_float(f2tf(v.y));
                v.z = __uint_as_float(f2tf(v.z)); v.w = __uint_as_float(f2tf(v.w));
                *(float4*)(&As[nb][row][q * 4]) = v;
            }
#pragma unroll
            for (int i = 0; i < 2; i++) {
                int u = tid + i * 256;
                int r = u >> 5, q = u & 31;
                *(float4*)(&Bs[nb][r][q * 4]) = rb[i];
            }
            __syncthreads();
        }
    }

    // epilogue
#pragma unroll
    for (int mt = 0; mt < 2; mt++)
#pragma unroll
        for (int nt = 0; nt < 8; nt++) {
            int row0 = rowBlock + wm * 32 + mt * 16 + g;
            int col  = colBlock + wn * 64 + nt * 8 + tg * 2;
            if (row0 < M)
                *(float2*)(C + (size_t)row0 * 256 + col) =
                    make_float2(acc[mt][nt][0], acc[mt][nt][1]);
            int row1 = row0 + 8;
            if (row1 < M)
                *(float2*)(C + (size_t)row1 * 256 + col) =
                    make_float2(acc[mt][nt][2], acc[mt][nt][3]);
        }
}

// ---------------------------------------------------------------------------
extern "C" void kernel_launch(void* const* d_in, const int* in_sizes, int n_in,
                              void* d_out, int out_size) {
    const float* x   = (const float*)d_in[0];
    const void*  ei  = d_in[1];
    const float* W1l = (const float*)d_in[2];
    const float* b1  = (const float*)d_in[3];
    const float* W1r = (const float*)d_in[4];
    const float* W2l = (const float*)d_in[5];
    const float* b2  = (const float*)d_in[6];
    const float* W2r = (const float*)d_in[7];
    float* out = (float*)d_out;

    const int M = in_sizes[0] / 384;
    const int E = in_sizes[1] / 2;

    float *pW1, *pW2, *pLin, *pAgg, *pH1, *pCnt;
    cudaGetSymbolAddress((void**)&pW1, g_W1);
    cudaGetSymbolAddress((void**)&pW2, g_W2);
    cudaGetSymbolAddress((void**)&pLin, g_lin);
    cudaGetSymbolAddress((void**)&pAgg, g_agg);
    cudaGetSymbolAddress((void**)&pH1, g_h1);
    cudaGetSymbolAddress((void**)&pCnt, g_cnt);

    const int T = 256;
    const size_t aggBytes = (size_t)M * 128 * sizeof(float);

    // setup: edge normalize + degree counts + tf32 weight packing
    detect_k<<<1, 1>>>((const unsigned*)ei);
    cudaMemsetAsync(pCnt, 0, (size_t)M * sizeof(float));
    prep_edges_k<<<(E + T - 1) / T, T>>>(ei, pCnt, E);
    pack_w_k<<<(384 * 256 + T - 1) / T, T>>>(W1l, W1r, pW1, 384);
    pack_w_k<<<(128 * 256 + T - 1) / T, T>>>(W2l, W2r, pW2, 128);

    dim3 gg(2, (M + 127) / 128);

    // ---- layer 1 ----
    gemm_tf32_k<<<gg, T>>>(x, pW1, pLin, M, 384);
    cudaMemsetAsync(pAgg, 0, aggBytes);
    scatter_k<<<(E * 32 + T - 1) / T, T>>>(pLin, pAgg, E);
    epilogue_k<<<(M * 32 + T - 1) / T, T>>>(pLin, pAgg, pCnt, b1, pH1, M, 1);

    // ---- layer 2 ----
    gemm_tf32_k<<<gg, T>>>(pH1, pW2, pLin, M, 128);
    cudaMemsetAsync(pAgg, 0, aggBytes);
    scatter_k<<<(E * 32 + T - 1) / T, T>>>(pLin, pAgg, E);
    epilogue_k<<<(M * 32 + T - 1) / T, T>>>(pLin, pAgg, pCnt, b2, out, M, 0);
}

// round 10
// speedup vs baseline: 1.7679x; 1.7304x over previous
#include <cuda_runtime.h>
#include <cuda_fp16.h>
#include <cstdint>
#include <cstddef>

// ---------------------------------------------------------------------------
// GraphSAGE 2-layer, GB300 sm_103a (base-PTX target: no tcgen05 available).
//   h1 = relu( segmean(x@W1l) + b1 + x@W1r )
//   out =      segmean(h1@W2l) + b2 + h1@W2r
// GEMMs fused as [K,256] = [W_l | W_r]; aggregation in projected 128-d space.
// GEMM: fp16 mma.sync.m16n8k16 (fp32 accum) — same 10-bit mantissa as tf32,
//       2x FLOP/instruction. A rounded to fp16 at smem staging; both A and B
//       fragments via ldmatrix.x4.
// Aggregation: CSR (degree hist + scan + fill), then warp-per-node gather
//       fused with mean/bias/root/relu — no atomics, no memset, no extra pass.
// ---------------------------------------------------------------------------

#define MAXN 100000
#define MAXE 200000

// scratch (static device globals: allocation-free contract)
__device__ __half g_W1[256 * 384];            // n-major [256][384]
__device__ __half g_W2[256 * 128];            // n-major [256][128]
__device__ float  g_lin[(size_t)MAXN * 256];
__device__ float  g_h1 [(size_t)MAXN * 128];
__device__ int    g_src[MAXE];
__device__ int    g_dst[MAXE];
__device__ int    g_deg[MAXN];
__device__ int    g_off[MAXN + 1];
__device__ int    g_cur[MAXN];
__device__ int    g_csr[MAXE];
__device__ int    g_partial[128];
__device__ int    g_is64;

__device__ __forceinline__ uint32_t smem_u32(const void* p) {
    uint32_t a;
    asm("{ .reg .u64 t; cvta.to.shared.u64 t, %1; cvt.u32.u64 %0, t; }"
        : "=r"(a) : "l"(p));
    return a;
}

__device__ __forceinline__ uint2 f4_to_h4(float4 v) {
    __half2 lo = __floats2half2_rn(v.x, v.y);
    __half2 hi = __floats2half2_rn(v.z, v.w);
    uint2 r;
    r.x = *reinterpret_cast<unsigned*>(&lo);
    r.y = *reinterpret_cast<unsigned*>(&hi);
    return r;
}

// ---------------- edge dtype detect + normalize + degree -------------------
__global__ void detect_k(const unsigned* __restrict__ w) {
    // int64 edges (nonneg, < 2^31) => all high words of first 64 entries are 0.
    int is64 = 1;
    for (int i = 0; i < 64; i++)
        if (w[2 * i + 1] != 0u) { is64 = 0; break; }
    g_is64 = is64;
}

__global__ void prep_edges_k(const void* __restrict__ ei, int E) {
    int i = blockIdx.x * blockDim.x + threadIdx.x;
    if (i >= E) return;
    int s, d;
    if (g_is64) {
        const long long* p = (const long long*)ei;
        s = (int)p[i];
        d = (int)p[E + i];
    } else {
        const int* p = (const int*)ei;
        s = p[i];
        d = p[E + i];
    }
    g_src[i] = s;
    g_dst[i] = d;
    atomicAdd(g_deg + d, 1);
}

// ---------------- CSR build: 1024 nodes per scan block ---------------------
__global__ void scan1_k(int M) {           // block partial sums of degrees
    __shared__ int sm[256];
    int base = blockIdx.x * 1024;
    int t = 0;
#pragma unroll
    for (int i = 0; i < 4; i++) {
        int n = base + threadIdx.x * 4 + i;
        if (n < M) t += g_deg[n];
    }
    sm[threadIdx.x] = t;
    __syncthreads();
    for (int o = 128; o > 0; o >>= 1) {
        if (threadIdx.x < o) sm[threadIdx.x] += sm[threadIdx.x + o];
        __syncthreads();
    }
    if (threadIdx.x == 0) g_partial[blockIdx.x] = sm[0];
}

__global__ void scan2_k(int NB, int M, int E) {   // exclusive scan of partials
    if (threadIdx.x == 0) {
        int run = 0;
        for (int b = 0; b < NB; b++) {
            int t = g_partial[b];
            g_partial[b] = run;
            run += t;
        }
        g_off[M] = E;
    }
}

__global__ void scan3_k(int M) {           // write offsets + cursors
    __shared__ int sm[256];
    int base = blockIdx.x * 1024;
    int d[4];
    int t = 0;
#pragma unroll
    for (int i = 0; i < 4; i++) {
        int n = base + threadIdx.x * 4 + i;
        d[i] = (n < M) ? g_deg[n] : 0;
        t += d[i];
    }
    sm[threadIdx.x] = t;
    __syncthreads();
    for (int o = 1; o < 256; o <<= 1) {     // Hillis-Steele inclusive scan
        int v = (threadIdx.x >= o) ? sm[threadIdx.x - o] : 0;
        __syncthreads();
        sm[threadIdx.x] += v;
        __syncthreads();
    }
    int run = g_partial[blockIdx.x] + sm[threadIdx.x] - t;   // exclusive
#pragma unroll
    for (int i = 0; i < 4; i++) {
        int n = base + threadIdx.x * 4 + i;
        if (n < M) { g_off[n] = run; g_cur[n] = run; run += d[i]; }
    }
}

__global__ void fill_k(int E) {
    int e = blockIdx.x * blockDim.x + threadIdx.x;
    if (e >= E) return;
    int pos = atomicAdd(g_cur + g_dst[e], 1);
    g_csr[pos] = g_src[e];
}

// ---------------- weight pack: [K,128]x2 -> fp16 n-major [256][K] ----------
__global__ void pack_w_k(const float* __restrict__ Wl, const float* __restrict__ Wr,
                         __half* __restrict__ Wc, int K) {
    int idx = blockIdx.x * blockDim.x + threadIdx.x;
    if (idx >= 256 * K) return;
    int n = idx / K, k = idx - n * K;
    float v = (n < 128) ? Wl[k * 128 + n] : Wr[k * 128 + n - 128];
    Wc[idx] = __float2half_rn(v);
}

// ---------------- fused gather: mean + bias + root (+relu) -----------------
// one warp per dst node; CSR in-edges; fully coalesced 512B row reads.
__global__ void gather_k(const float* __restrict__ lin, const float* __restrict__ bias,
                         float* __restrict__ out, int M, int do_relu) {
    int gt = blockIdx.x * blockDim.x + threadIdx.x;
    int node = gt >> 5, lane = gt & 31;
    if (node >= M) return;
    int e0 = g_off[node], e1 = g_off[node + 1];
    float4 a = make_float4(0.f, 0.f, 0.f, 0.f);
    for (int e = e0; e < e1; e++) {
        int s = g_csr[e];
        float4 v = *(const float4*)(lin + (size_t)s * 256 + lane * 4);
        a.x += v.x; a.y += v.y; a.z += v.z; a.w += v.w;
    }
    float inv = 1.0f / fmaxf((float)(e1 - e0), 1.0f);
    float4 r = *(const float4*)(lin + (size_t)node * 256 + 128 + lane * 4);
    float4 b = *(const float4*)(bias + lane * 4);
    float4 o;
    o.x = fmaf(a.x, inv, b.x) + r.x;
    o.y = fmaf(a.y, inv, b.y) + r.y;
    o.z = fmaf(a.z, inv, b.z) + r.z;
    o.w = fmaf(a.w, inv, b.w) + r.w;
    if (do_relu) {
        o.x = fmaxf(o.x, 0.f); o.y = fmaxf(o.y, 0.f);
        o.z = fmaxf(o.z, 0.f); o.w = fmaxf(o.w, 0.f);
    }
    *(float4*)(out + (size_t)node * 128 + lane * 4) = o;
}

// ---------------- fp16 GEMM: C[M,256] = A[M,K] @ W^T (W = [256,K]) ---------
// block tile 128 rows x 128 cols (grid.x=2 col-blocks adjacent for A L2 reuse)
// BK=32, 8 warps (4x2), warp tile 32x64, mma.m16n8k16 fp32-accum,
// double-buffered smem, A+B fragments via ldmatrix.x4.
__global__ __launch_bounds__(256, 2) void gemm_fp16_k(
    const float* __restrict__ A, const __half* __restrict__ W,
    float* __restrict__ C, int M, int K)
{
    __shared__ __align__(16) __half As[2][128][40];   // stride 80B: LDSM-conflict-free
    __shared__ __align__(16) __half Bs[2][128][40];   // n-major [n][k]

    const int tid = threadIdx.x;
    const int warp = tid >> 5, lane = tid & 31;
    const int wm = warp >> 1, wn = warp & 1;
    const int g = lane >> 2, tg = lane & 3;
    const int colBlock = blockIdx.x * 128;
    const int rowBlock = blockIdx.y * 128;

    float acc[2][8][4];
#pragma unroll
    for (int i = 0; i < 2; i++)
#pragma unroll
        for (int j = 0; j < 8; j++)
#pragma unroll
            for (int k = 0; k < 4; k++) acc[i][j][k] = 0.f;

    const int NT = K >> 5;

    const uint32_t asb[2] = { smem_u32(&As[0][0][0]), smem_u32(&As[1][0][0]) };
    const uint32_t bsb[2] = { smem_u32(&Bs[0][0][0]), smem_u32(&Bs[1][0][0]) };
    // A frags, m8n8.x4 b16: lanes 0-7 m0(rows0-7,k0-7), 8-15 m1(rows8-15,k0-7),
    // 16-23 m2(rows0-7,k8-15), 24-31 m3(rows8-15,k8-15) -> regs a0..a3.
    const uint32_t aoff = ((wm * 32 + (lane & 15)) * 40 + (lane >> 4) * 8) * 2;
    // B frags: m0(n0-7,k0-7) m1(n0-7,k8-15) m2(n8-15,k0-7) m3(n8-15,k8-15)
    const uint32_t boff = ((wn * 64 + ((lane >> 4) * 8) + (lane & 7)) * 40
                           + ((lane >> 3) & 1) * 8) * 2;

    // prologue: tile 0 -> buf 0
    {
#pragma unroll
        for (int i = 0; i < 4; i++) {
            int u = tid + i * 256;
            int row = u >> 3, q = u & 7;
            int gr = rowBlock + row;
            float4 v = make_float4(0.f, 0.f, 0.f, 0.f);
            if (gr < M) v = *(const float4*)(A + (size_t)gr * K + q * 4);
            *(uint2*)(&As[0][row][q * 4]) = f4_to_h4(v);
        }
#pragma unroll
        for (int i = 0; i < 4; i++) {
            int u = tid + i * 256;
            int row = u >> 3, q = u & 7;
            *(uint2*)(&Bs[0][row][q * 4]) =
                *(const uint2*)(W + (size_t)(colBlock + row) * K + q * 4);
        }
    }
    __syncthreads();

    float4 ra[4];
    uint2  rb[4];
    for (int kt = 0; kt < NT; kt++) {
        const int cur = kt & 1;
        if (kt + 1 < NT) {
            const int k0 = (kt + 1) << 5;
#pragma unroll
            for (int i = 0; i < 4; i++) {
                int u = tid + i * 256;
                int row = u >> 3, q = u & 7;
                int gr = rowBlock + row;
                ra[i] = make_float4(0.f, 0.f, 0.f, 0.f);
                if (gr < M) ra[i] = *(const float4*)(A + (size_t)gr * K + k0 + q * 4);
            }
#pragma unroll
            for (int i = 0; i < 4; i++) {
                int u = tid + i * 256;
                int row = u >> 3, q = u & 7;
                rb[i] = *(const uint2*)(W + (size_t)(colBlock + row) * K + k0 + q * 4);
            }
        }

#pragma unroll
        for (int ks = 0; ks < 2; ks++) {
            unsigned a[2][4];
#pragma unroll
            for (int mt = 0; mt < 2; mt++) {
                uint32_t addr = asb[cur] + aoff + mt * 1280 + ks * 32;
                asm volatile(
                    "ldmatrix.sync.aligned.m8n8.x4.shared.b16 {%0,%1,%2,%3}, [%4];"
                    : "=r"(a[mt][0]), "=r"(a[mt][1]), "=r"(a[mt][2]), "=r"(a[mt][3])
                    : "r"(addr));
            }
            unsigned b[8][2];
#pragma unroll
            for (int p = 0; p < 4; p++) {
                uint32_t addr = bsb[cur] + boff + p * 1280 + ks * 32;
                asm volatile(
                    "ldmatrix.sync.aligned.m8n8.x4.shared.b16 {%0,%1,%2,%3}, [%4];"
                    : "=r"(b[2 * p][0]), "=r"(b[2 * p][1]),
                      "=r"(b[2 * p + 1][0]), "=r"(b[2 * p + 1][1])
                    : "r"(addr));
            }
#pragma unroll
            for (int mt = 0; mt < 2; mt++)
#pragma unroll
                for (int nt = 0; nt < 8; nt++) {
                    asm volatile(
                        "mma.sync.aligned.m16n8k16.row.col.f32.f16.f16.f32 "
                        "{%0,%1,%2,%3}, {%4,%5,%6,%7}, {%8,%9}, {%0,%1,%2,%3};\n"
                        : "+f"(acc[mt][nt][0]), "+f"(acc[mt][nt][1]),
                          "+f"(acc[mt][nt][2]), "+f"(acc[mt][nt][3])
                        : "r"(a[mt][0]), "r"(a[mt][1]), "r"(a[mt][2]), "r"(a[mt][3]),
                          "r"(b[nt][0]), "r"(b[nt][1]));
                }
        }
        __syncthreads();
        if (kt + 1 < NT) {
            const int nb = cur ^ 1;
#pragma unroll
            for (int i = 0; i < 4; i++) {
                int u = tid + i * 256;
                int row = u >> 3, q = u & 7;
                *(uint2*)(&As[nb][row][q * 4]) = f4_to_h4(ra[i]);
            }
#pragma unroll
            for (int i = 0; i < 4; i++) {
                int u = tid + i * 256;
                int row = u >> 3, q = u & 7;
                *(uint2*)(&Bs[nb][row][q * 4]) = rb[i];
            }
            __syncthreads();
        }
    }

    // epilogue (m16n8 C layout: c0,c1 row g; c2,c3 row g+8; cols tg*2,+1)
#pragma unroll
    for (int mt = 0; mt < 2; mt++)
#pragma unroll
        for (int nt = 0; nt < 8; nt++) {
            int row0 = rowBlock + wm * 32 + mt * 16 + g;
            int col  = colBlock + wn * 64 + nt * 8 + tg * 2;
            if (row0 < M)
                *(float2*)(C + (size_t)row0 * 256 + col) =
                    make_float2(acc[mt][nt][0], acc[mt][nt][1]);
            int row1 = row0 + 8;
            if (row1 < M)
                *(float2*)(C + (size_t)row1 * 256 + col) =
                    make_float2(acc[mt][nt][2], acc[mt][nt][3]);
        }
}

// ---------------------------------------------------------------------------
extern "C" void kernel_launch(void* const* d_in, const int* in_sizes, int n_in,
                              void* d_out, int out_size) {
    const float* x   = (const float*)d_in[0];
    const void*  ei  = d_in[1];
    const float* W1l = (const float*)d_in[2];
    const float* b1  = (const float*)d_in[3];
    const float* W1r = (const float*)d_in[4];
    const float* W2l = (const float*)d_in[5];
    const float* b2  = (const float*)d_in[6];
    const float* W2r = (const float*)d_in[7];
    float* out = (float*)d_out;

    const int M = in_sizes[0] / 384;
    const int E = in_sizes[1] / 2;
    const int NB = (M + 1023) / 1024;

    float *pLin, *pH1;
    __half *pW1, *pW2;
    int *pDeg;
    cudaGetSymbolAddress((void**)&pLin, g_lin);
    cudaGetSymbolAddress((void**)&pH1, g_h1);
    cudaGetSymbolAddress((void**)&pW1, g_W1);
    cudaGetSymbolAddress((void**)&pW2, g_W2);
    cudaGetSymbolAddress((void**)&pDeg, g_deg);

    const int T = 256;

    // setup: edges -> CSR, weights -> fp16 n-major
    detect_k<<<1, 1>>>((const unsigned*)ei);
    cudaMemsetAsync(pDeg, 0, (size_t)M * sizeof(int));
    prep_edges_k<<<(E + T - 1) / T, T>>>(ei, E);
    scan1_k<<<NB, T>>>(M);
    scan2_k<<<1, 32>>>(NB, M, E);
    scan3_k<<<NB, T>>>(M);
    fill_k<<<(E + T - 1) / T, T>>>(E);
    pack_w_k<<<(256 * 384 + T - 1) / T, T>>>(W1l, W1r, pW1, 384);
    pack_w_k<<<(256 * 128 + T - 1) / T, T>>>(W2l, W2r, pW2, 128);

    dim3 gg(2, (M + 127) / 128);
    const int gatherBlocks = (M * 32 + T - 1) / T;

    // ---- layer 1 ----
    gemm_fp16_k<<<gg, T>>>(x, pW1, pLin, M, 384);
    gather_k<<<gatherBlocks, T>>>(pLin, b1, pH1, M, 1);

    // ---- layer 2 ----
    gemm_fp16_k<<<gg, T>>>(pH1, pW2, pLin, M, 128);
    gather_k<<<gatherBlocks, T>>>(pLin, b2, out, M, 0);
}

// round 11
// speedup vs baseline: 1.9831x; 1.1217x over previous
#include <cuda_runtime.h>
#include <cuda_fp16.h>
#include <cstdint>
#include <cstddef>

// ---------------------------------------------------------------------------
// GraphSAGE 2-layer, GB300 sm_103a (base-PTX target: no tcgen05 available).
//   h1 = relu( segmean(x@W1l) + b1 + x@W1r )
//   out =      segmean(h1@W2l) + b2 + h1@W2r
// GEMMs fused as [K,256] = [W_l | W_r]; aggregation in projected 128-d space.
// GEMM: fp16 mma.sync.m16n8k16 (fp32 accum); A/B frags via ldmatrix.x4.
// Intermediates (lin, h1) stored fp16: halves epilogue/gather/GEMM2-A traffic;
// GEMM2 rounded A to fp16 anyway, so h1-fp16 adds no new error.
// Aggregation: CSR (hist + 2-kernel scan + fill) then warp-per-node gather
// fused with mean/bias/root/relu. fp16 lin (51MB) ~fits L2 -> gather L2-hits.
// ---------------------------------------------------------------------------

#define MAXN 100000
#define MAXE 200000

// scratch (static device globals: allocation-free contract)
__device__ __half g_W1[256 * 384];            // n-major [256][384]
__device__ __half g_W2[256 * 128];            // n-major [256][128]
__device__ __half g_lin[(size_t)MAXN * 256];
__device__ __half g_h1 [(size_t)MAXN * 128];
__device__ int    g_src[MAXE];
__device__ int    g_dst[MAXE];
__device__ int    g_deg[MAXN];
__device__ int    g_off[MAXN + 1];
__device__ int    g_cur[MAXN];
__device__ int    g_csr[MAXE];
__device__ int    g_partial[256];
__device__ int    g_is64;

__device__ __forceinline__ uint32_t smem_u32(const void* p) {
    uint32_t a;
    asm("{ .reg .u64 t; cvta.to.shared.u64 t, %1; cvt.u32.u64 %0, t; }"
        : "=r"(a) : "l"(p));
    return a;
}

__device__ __forceinline__ uint2 f4_to_h4(float4 v) {
    __half2 lo = __floats2half2_rn(v.x, v.y);
    __half2 hi = __floats2half2_rn(v.z, v.w);
    uint2 r;
    r.x = *reinterpret_cast<unsigned*>(&lo);
    r.y = *reinterpret_cast<unsigned*>(&hi);
    return r;
}

// ---------------- edge dtype detect (1 warp, ballot) -----------------------
__global__ void detect_k(const unsigned* __restrict__ w) {
    // int64 edges (nonneg, < 2^31) => all high words of first 64 entries are 0.
    int lane = threadIdx.x;
    unsigned bad = (w[2 * lane + 1] != 0u) || (w[2 * (lane + 32) + 1] != 0u);
    unsigned m = __ballot_sync(0xFFFFFFFFu, bad);
    if (lane == 0) g_is64 = (m == 0u);
}

__global__ void prep_edges_k(const void* __restrict__ ei, int E) {
    int i = blockIdx.x * blockDim.x + threadIdx.x;
    if (i >= E) return;
    int s, d;
    if (g_is64) {
        const long long* p = (const long long*)ei;
        s = (int)p[i];
        d = (int)p[E + i];
    } else {
        const int* p = (const int*)ei;
        s = p[i];
        d = p[E + i];
    }
    g_src[i] = s;
    g_dst[i] = d;
    atomicAdd(g_deg + d, 1);
}

// ---------------- CSR build: 1024 nodes per scan block ---------------------
__global__ void scan1_k(int M) {           // block partial sums of degrees
    __shared__ int sm[256];
    int base = blockIdx.x * 1024;
    int t = 0;
#pragma unroll
    for (int i = 0; i < 4; i++) {
        int n = base + threadIdx.x * 4 + i;
        if (n < M) t += g_deg[n];
    }
    sm[threadIdx.x] = t;
    __syncthreads();
    for (int o = 128; o > 0; o >>= 1) {
        if (threadIdx.x < o) sm[threadIdx.x] += sm[threadIdx.x + o];
        __syncthreads();
    }
    if (threadIdx.x == 0) g_partial[blockIdx.x] = sm[0];
}

// offsets + cursors; each block derives its own prefix of partials (NB<256)
__global__ void scan3_k(int M, int E) {
    __shared__ int sm[256], sp[256];
    int tid = threadIdx.x;
    sp[tid] = (tid < blockIdx.x) ? g_partial[tid] : 0;

    int base = blockIdx.x * 1024;
    int d[4];
    int t = 0;
#pragma unroll
    for (int i = 0; i < 4; i++) {
        int n = base + tid * 4 + i;
        d[i] = (n < M) ? g_deg[n] : 0;
        t += d[i];
    }
    sm[tid] = t;
    __syncthreads();
    for (int o = 128; o > 0; o >>= 1) {    // reduce partial-prefix
        if (tid < o) sp[tid] += sp[tid + o];
        __syncthreads();
    }
    for (int o = 1; o < 256; o <<= 1) {    // Hillis-Steele inclusive scan
        int v = (tid >= o) ? sm[tid - o] : 0;
        __syncthreads();
        sm[tid] += v;
        __syncthreads();
    }
    int run = sp[0] + sm[tid] - t;         // exclusive within-block + prefix
#pragma unroll
    for (int i = 0; i < 4; i++) {
        int n = base + tid * 4 + i;
        if (n < M) { g_off[n] = run; g_cur[n] = run; run += d[i]; }
    }
    if (blockIdx.x == 0 && tid == 0) g_off[M] = E;
}

__global__ void fill_k(int E) {
    int e = blockIdx.x * blockDim.x + threadIdx.x;
    if (e >= E) return;
    int pos = atomicAdd(g_cur + g_dst[e], 1);
    g_csr[pos] = g_src[e];
}

// ---------------- weight pack: [K,128]x2 -> fp16 n-major [256][K] ----------
__global__ void pack_w_k(const float* __restrict__ Wl, const float* __restrict__ Wr,
                         __half* __restrict__ Wc, int K) {
    int idx = blockIdx.x * blockDim.x + threadIdx.x;
    if (idx >= 256 * K) return;
    int n = idx / K, k = idx - n * K;
    float v = (n < 128) ? Wl[k * 128 + n] : Wr[k * 128 + n - 128];
    Wc[idx] = __float2half_rn(v);
}

// ---------------- fused gather: mean + bias + root (+relu) -----------------
// one warp per dst node; CSR in-edges; coalesced 256B fp16 row reads.
// OUTHALF=1: relu + fp16 output (layer 1); OUTHALF=0: fp32 output (layer 2).
template <int OUTHALF>
__global__ void gather_k(const __half* __restrict__ lin, const float* __restrict__ bias,
                         void* __restrict__ outv, int M) {
    int gt = blockIdx.x * blockDim.x + threadIdx.x;
    int node = gt >> 5, lane = gt & 31;
    if (node >= M) return;
    int e0 = g_off[node], e1 = g_off[node + 1];
    float4 a = make_float4(0.f, 0.f, 0.f, 0.f);
    for (int e = e0; e < e1; e++) {
        int s = g_csr[e];
        uint2 u = *(const uint2*)(lin + (size_t)s * 256 + lane * 4);
        float2 f0 = __half22float2(*reinterpret_cast<__half2*>(&u.x));
        float2 f1 = __half22float2(*reinterpret_cast<__half2*>(&u.y));
        a.x += f0.x; a.y += f0.y; a.z += f1.x; a.w += f1.y;
    }
    float inv = 1.0f / fmaxf((float)(e1 - e0), 1.0f);
    uint2 ru = *(const uint2*)(lin + (size_t)node * 256 + 128 + lane * 4);
    float2 r0 = __half22float2(*reinterpret_cast<__half2*>(&ru.x));
    float2 r1 = __half22float2(*reinterpret_cast<__half2*>(&ru.y));
    float4 b = *(const float4*)(bias + lane * 4);
    float4 o;
    o.x = fmaf(a.x, inv, b.x) + r0.x;
    o.y = fmaf(a.y, inv, b.y) + r0.y;
    o.z = fmaf(a.z, inv, b.z) + r1.x;
    o.w = fmaf(a.w, inv, b.w) + r1.y;
    if (OUTHALF) {
        o.x = fmaxf(o.x, 0.f); o.y = fmaxf(o.y, 0.f);
        o.z = fmaxf(o.z, 0.f); o.w = fmaxf(o.w, 0.f);
        *(uint2*)((__half*)outv + (size_t)node * 128 + lane * 4) = f4_to_h4(o);
    } else {
        *(float4*)((float*)outv + (size_t)node * 128 + lane * 4) = o;
    }
}

// ---------------- fp16 GEMM: C[M,256] = A[M,K] @ W^T (W = [256,K]) ---------
// block tile 128 rows x 128 cols (grid.x=2 col-blocks adjacent for A L2 reuse)
// BK=32, 8 warps (4x2), warp tile 32x64, mma.m16n8k16 fp32-accum,
// double-buffered smem, A+B fragments via ldmatrix.x4, fp16 C output.
// AHALF=0: A fp32 (converted at staging); AHALF=1: A already fp16.
template <int AHALF>
__global__ __launch_bounds__(256, 2) void gemm_fp16_k(
    const void* __restrict__ Av, const __half* __restrict__ W,
    __half* __restrict__ C, int M, int K)
{
    const float* A32 = (const float*)Av;
    const __half* A16 = (const __half*)Av;

    __shared__ __align__(16) __half As[2][128][40];   // stride 80B: LDSM-conflict-free
    __shared__ __align__(16) __half Bs[2][128][40];   // n-major [n][k]

    const int tid = threadIdx.x;
    const int warp = tid >> 5, lane = tid & 31;
    const int wm = warp >> 1, wn = warp & 1;
    const int g = lane >> 2, tg = lane & 3;
    const int colBlock = blockIdx.x * 128;
    const int rowBlock = blockIdx.y * 128;

    float acc[2][8][4];
#pragma unroll
    for (int i = 0; i < 2; i++)
#pragma unroll
        for (int j = 0; j < 8; j++)
#pragma unroll
            for (int k = 0; k < 4; k++) acc[i][j][k] = 0.f;

    const int NT = K >> 5;

    const uint32_t asb[2] = { smem_u32(&As[0][0][0]), smem_u32(&As[1][0][0]) };
    const uint32_t bsb[2] = { smem_u32(&Bs[0][0][0]), smem_u32(&Bs[1][0][0]) };
    // A frags, m8n8.x4 b16: lanes 0-7 m0(rows0-7,k0-7), 8-15 m1(rows8-15,k0-7),
    // 16-23 m2(rows0-7,k8-15), 24-31 m3(rows8-15,k8-15) -> regs a0..a3.
    const uint32_t aoff = ((wm * 32 + (lane & 15)) * 40 + (lane >> 4) * 8) * 2;
    // B frags: m0(n0-7,k0-7) m1(n0-7,k8-15) m2(n8-15,k0-7) m3(n8-15,k8-15)
    const uint32_t boff = ((wn * 64 + ((lane >> 4) * 8) + (lane & 7)) * 40
                           + ((lane >> 3) & 1) * 8) * 2;

    // prologue: tile 0 -> buf 0
    {
#pragma unroll
        for (int i = 0; i < 4; i++) {
            int u = tid + i * 256;
            int row = u >> 3, q = u & 7;
            int gr = rowBlock + row;
            uint2 h;
            if (AHALF) {
                h = make_uint2(0u, 0u);
                if (gr < M) h = *(const uint2*)(A16 + (size_t)gr * K + q * 4);
            } else {
                float4 v = make_float4(0.f, 0.f, 0.f, 0.f);
                if (gr < M) v = *(const float4*)(A32 + (size_t)gr * K + q * 4);
                h = f4_to_h4(v);
            }
            *(uint2*)(&As[0][row][q * 4]) = h;
        }
#pragma unroll
        for (int i = 0; i < 4; i++) {
            int u = tid + i * 256;
            int row = u >> 3, q = u & 7;
            *(uint2*)(&Bs[0][row][q * 4]) =
                *(const uint2*)(W + (size_t)(colBlock + row) * K + q * 4);
        }
    }
    __syncthreads();

    float4 ra32[4];
    uint2  ra16[4];
    uint2  rb[4];
    for (int kt = 0; kt < NT; kt++) {
        const int cur = kt & 1;
        if (kt + 1 < NT) {
            const int k0 = (kt + 1) << 5;
#pragma unroll
            for (int i = 0; i < 4; i++) {
                int u = tid + i * 256;
                int row = u >> 3, q = u & 7;
                int gr = rowBlock + row;
                if (AHALF) {
                    ra16[i] = make_uint2(0u, 0u);
                    if (gr < M) ra16[i] = *(const uint2*)(A16 + (size_t)gr * K + k0 + q * 4);
                } else {
                    ra32[i] = make_float4(0.f, 0.f, 0.f, 0.f);
                    if (gr < M) ra32[i] = *(const float4*)(A32 + (size_t)gr * K + k0 + q * 4);
                }
            }
#pragma unroll
            for (int i = 0; i < 4; i++) {
                int u = tid + i * 256;
                int row = u >> 3, q = u & 7;
                rb[i] = *(const uint2*)(W + (size_t)(colBlock + row) * K + k0 + q * 4);
            }
        }

#pragma unroll
        for (int ks = 0; ks < 2; ks++) {
            unsigned a[2][4];
#pragma unroll
            for (int mt = 0; mt < 2; mt++) {
                uint32_t addr = asb[cur] + aoff + mt * 1280 + ks * 32;
                asm volatile(
                    "ldmatrix.sync.aligned.m8n8.x4.shared.b16 {%0,%1,%2,%3}, [%4];"
                    : "=r"(a[mt][0]), "=r"(a[mt][1]), "=r"(a[mt][2]), "=r"(a[mt][3])
                    : "r"(addr));
            }
            unsigned b[8][2];
#pragma unroll
            for (int p = 0; p < 4; p++) {
                uint32_t addr = bsb[cur] + boff + p * 1280 + ks * 32;
                asm volatile(
                    "ldmatrix.sync.aligned.m8n8.x4.shared.b16 {%0,%1,%2,%3}, [%4];"
                    : "=r"(b[2 * p][0]), "=r"(b[2 * p][1]),
                      "=r"(b[2 * p + 1][0]), "=r"(b[2 * p + 1][1])
                    : "r"(addr));
            }
#pragma unroll
            for (int mt = 0; mt < 2; mt++)
#pragma unroll
                for (int nt = 0; nt < 8; nt++) {
                    asm volatile(
                        "mma.sync.aligned.m16n8k16.row.col.f32.f16.f16.f32 "
                        "{%0,%1,%2,%3}, {%4,%5,%6,%7}, {%8,%9}, {%0,%1,%2,%3};\n"
                        : "+f"(acc[mt][nt][0]), "+f"(acc[mt][nt][1]),
                          "+f"(acc[mt][nt][2]), "+f"(acc[mt][nt][3])
                        : "r"(a[mt][0]), "r"(a[mt][1]), "r"(a[mt][2]), "r"(a[mt][3]),
                          "r"(b[nt][0]), "r"(b[nt][1]));
                }
        }
        __syncthreads();
        if (kt + 1 < NT) {
            const int nb = cur ^ 1;
#pragma unroll
            for (int i = 0; i < 4; i++) {
                int u = tid + i * 256;
                int row = u >> 3, q = u & 7;
                *(uint2*)(&As[nb][row][q * 4]) = AHALF ? ra16[i] : f4_to_h4(ra32[i]);
            }
#pragma unroll
            for (int i = 0; i < 4; i++) {
                int u = tid + i * 256;
                int row = u >> 3, q = u & 7;
                *(uint2*)(&Bs[nb][row][q * 4]) = rb[i];
            }
            __syncthreads();
        }
    }

    // epilogue, fp16 C (m16n8: c0,c1 row g; c2,c3 row g+8; cols tg*2,+1)
#pragma unroll
    for (int mt = 0; mt < 2; mt++)
#pragma unroll
        for (int nt = 0; nt < 8; nt++) {
            int row0 = rowBlock + wm * 32 + mt * 16 + g;
            int col  = colBlock + wn * 64 + nt * 8 + tg * 2;
            if (row0 < M)
                *(__half2*)(C + (size_t)row0 * 256 + col) =
                    __floats2half2_rn(acc[mt][nt][0], acc[mt][nt][1]);
            int row1 = row0 + 8;
            if (row1 < M)
                *(__half2*)(C + (size_t)row1 * 256 + col) =
                    __floats2half2_rn(acc[mt][nt][2], acc[mt][nt][3]);
        }
}

// ---------------------------------------------------------------------------
extern "C" void kernel_launch(void* const* d_in, const int* in_sizes, int n_in,
                              void* d_out, int out_size) {
    const float* x   = (const float*)d_in[0];
    const void*  ei  = d_in[1];
    const float* W1l = (const float*)d_in[2];
    const float* b1  = (const float*)d_in[3];
    const float* W1r = (const float*)d_in[4];
    const float* W2l = (const float*)d_in[5];
    const float* b2  = (const float*)d_in[6];
    const float* W2r = (const float*)d_in[7];
    float* out = (float*)d_out;

    const int M = in_sizes[0] / 384;
    const int E = in_sizes[1] / 2;
    const int NB = (M + 1023) / 1024;

    __half *pW1, *pW2, *pLin, *pH1;
    int *pDeg;
    cudaGetSymbolAddress((void**)&pLin, g_lin);
    cudaGetSymbolAddress((void**)&pH1, g_h1);
    cudaGetSymbolAddress((void**)&pW1, g_W1);
    cudaGetSymbolAddress((void**)&pW2, g_W2);
    cudaGetSymbolAddress((void**)&pDeg, g_deg);

    const int T = 256;

    // setup: edges -> CSR, weights -> fp16 n-major
    detect_k<<<1, 32>>>((const unsigned*)ei);
    cudaMemsetAsync(pDeg, 0, (size_t)M * sizeof(int));
    prep_edges_k<<<(E + T - 1) / T, T>>>(ei, E);
    scan1_k<<<NB, T>>>(M);
    scan3_k<<<NB, T>>>(M, E);
    fill_k<<<(E + T - 1) / T, T>>>(E);
    pack_w_k<<<(256 * 384 + T - 1) / T, T>>>(W1l, W1r, pW1, 384);
    pack_w_k<<<(256 * 128 + T - 1) / T, T>>>(W2l, W2r, pW2, 128);

    dim3 gg(2, (M + 127) / 128);
    const int gatherBlocks = (M * 32 + T - 1) / T;

    // ---- layer 1 ----
    gemm_fp16_k<0><<<gg, T>>>(x, pW1, pLin, M, 384);
    gather_k<1><<<gatherBlocks, T>>>(pLin, b1, pH1, M);

    // ---- layer 2 ----
    gemm_fp16_k<1><<<gg, T>>>(pH1, pW2, pLin, M, 128);
    gather_k<0><<<gatherBlocks, T>>>(pLin, b2, out, M);
}

// round 13
// speedup vs baseline: 2.0444x; 1.0309x over previous
#include <cuda_runtime.h>
#include <cuda_fp16.h>
#include <cstdint>
#include <cstddef>

// ---------------------------------------------------------------------------
// GraphSAGE 2-layer, GB300 sm_103a (base-PTX target: no tcgen05 available).
//   h1 = relu( segmean(x@W1l) + b1 + x@W1r )
//   out =      segmean(h1@W2l) + b2 + h1@W2r
// GEMMs fused as [K,256] = [W_l | W_r]; aggregation in projected 128-d space.
// GEMM: fp16 mma.sync.m16n8k16 (fp32 accum), BK=64, ONE barrier per K-slice
//       (double-buffer with direct LDG->STS prefetch), ldmatrix.x4 frags.
// Intermediates (lin, h1) fp16. CSR via single windowed-lookback scan.
// R13 fix: weight pointers via cudaGetSymbolAddress (R12 passed __device__
// symbols as host-side kernel args -> host shadow address -> garbage B).
// ---------------------------------------------------------------------------

#define MAXN 100000
#define MAXE 200000

// scratch (static device globals: allocation-free contract)
__device__ __half g_W1[256 * 384];            // n-major [256][384]
__device__ __half g_W2[256 * 128];            // n-major [256][128]
__device__ __half g_lin[(size_t)MAXN * 256];
__device__ __half g_h1 [(size_t)MAXN * 128];
__device__ int    g_src[MAXE];
__device__ int    g_dst[MAXE];
__device__ int    g_deg[MAXN];
__device__ int    g_off[MAXN + 1];
__device__ int    g_cur[MAXN];
__device__ int    g_csr[MAXE];
__device__ int    g_look[128];                // lookback slots: agg+1, 0=not ready

__device__ __forceinline__ uint32_t smem_u32(const void* p) {
    uint32_t a;
    asm("{ .reg .u64 t; cvta.to.shared.u64 t, %1; cvt.u32.u64 %0, t; }"
        : "=r"(a) : "l"(p));
    return a;
}

__device__ __forceinline__ uint2 f4_to_h4(float4 v) {
    __half2 lo = __floats2half2_rn(v.x, v.y);
    __half2 hi = __floats2half2_rn(v.z, v.w);
    uint2 r;
    r.x = *reinterpret_cast<unsigned*>(&lo);
    r.y = *reinterpret_cast<unsigned*>(&hi);
    return r;
}

// ---------------- edges: dtype detect (per block) + normalize + degree -----
__global__ void prep_edges_k(const void* __restrict__ ei, int E) {
    __shared__ int s_bad;
    if (threadIdx.x == 0) s_bad = 0;
    __syncthreads();
    // int64 edges (nonneg, < 2^31) => all high words of first 64 entries are 0
    const unsigned* w = (const unsigned*)ei;
    if (threadIdx.x < 64 && w[2 * threadIdx.x + 1] != 0u) s_bad = 1;
    __syncthreads();
    const int is64 = !s_bad;

    int gt = blockIdx.x * blockDim.x + threadIdx.x;
    if (gt < 128) g_look[gt] = 0;          // reset lookback slots each replay
    if (gt >= E) return;
    int s, d;
    if (is64) {
        const long long* p = (const long long*)ei;
        s = (int)p[gt];
        d = (int)p[E + gt];
    } else {
        const int* p = (const int*)ei;
        s = p[gt];
        d = p[E + gt];
    }
    g_src[gt] = s;
    g_dst[gt] = d;
    atomicAdd(g_deg + d, 1);
}

// ---------------- CSR offsets: single-pass windowed-lookback scan ----------
// 1024 nodes per block; all blocks resident (NB<=98 < 148 SMs): spin is safe.
__global__ void scan_k(int M, int E) {
    __shared__ int wsum[8];
    __shared__ int sprefix;
    const int tid = threadIdx.x, lane = tid & 31, wid = tid >> 5;
    const int b = blockIdx.x;
    const int base = b * 1024 + tid * 4;

    int d[4], sum4 = 0;
#pragma unroll
    for (int i = 0; i < 4; i++) {
        int n = base + i;
        d[i] = (n < M) ? g_deg[n] : 0;
        sum4 += d[i];
    }
    // warp inclusive scan of per-thread sums
    int t = sum4;
#pragma unroll
    for (int o = 1; o < 32; o <<= 1) {
        int v = __shfl_up_sync(0xFFFFFFFFu, t, o);
        if (lane >= o) t += v;
    }
    if (lane == 31) wsum[wid] = t;
    __syncthreads();
    if (tid < 8) {
        int wv = wsum[tid];
#pragma unroll
        for (int o = 1; o < 8; o <<= 1) {
            int v = __shfl_up_sync(0xFFu, wv, o);
            if (tid >= o) wv += v;
        }
        wsum[tid] = wv;                    // inclusive warp prefix
    }
    __syncthreads();

    // publish block aggregate (value+1, single word: no fence needed)
    if (tid == 0) *((volatile int*)&g_look[b]) = wsum[7] + 1;

    // windowed lookback: warp 0 sums all predecessor aggregates in parallel
    if (wid == 0) {
        int pre = 0;
        for (int s0 = 0; s0 < b; s0 += 32) {
            int i = s0 + lane, v = 0;
            if (i < b) {
                volatile int* p = &g_look[i];
                do { v = *p; } while (v == 0);
                v -= 1;
            }
            pre += v;
        }
#pragma unroll
        for (int o = 16; o > 0; o >>= 1) pre += __shfl_xor_sync(0xFFFFFFFFu, pre, o);
        if (lane == 0) sprefix = pre;
    }
    __syncthreads();

    int run = sprefix + (t - sum4) + (wid > 0 ? wsum[wid - 1] : 0);
#pragma unroll
    for (int i = 0; i < 4; i++) {
        int n = base + i;
        if (n < M) { g_off[n] = run; g_cur[n] = run; run += d[i]; }
    }
    if (b == 0 && tid == 0) g_off[M] = E;
}

__global__ void fill_k(int E) {
    int e = blockIdx.x * blockDim.x + threadIdx.x;
    if (e >= E) return;
    int pos = atomicAdd(g_cur + g_dst[e], 1);
    g_csr[pos] = g_src[e];
}

// ---------------- weight pack (both layers): fp16 n-major [256][K] ---------
__global__ void pack_all_k(const float* __restrict__ W1l, const float* __restrict__ W1r,
                           const float* __restrict__ W2l, const float* __restrict__ W2r) {
    int idx = blockIdx.x * blockDim.x + threadIdx.x;
    if (idx < 256 * 384) {
        int n = idx / 384, k = idx - n * 384;
        float v = (n < 128) ? W1l[k * 128 + n] : W1r[k * 128 + n - 128];
        g_W1[idx] = __float2half_rn(v);
    } else if (idx < 256 * 384 + 256 * 128) {
        int j = idx - 256 * 384;
        int n = j >> 7, k = j & 127;
        float v = (n < 128) ? W2l[k * 128 + n] : W2r[k * 128 + n - 128];
        g_W2[j] = __float2half_rn(v);
    }
}

// ---------------- fused gather: mean + bias + root (+relu) -----------------
// one warp per dst node; CSR in-edges; coalesced 256B fp16 row reads.
template <int OUTHALF>
__global__ void gather_k(const __half* __restrict__ lin, const float* __restrict__ bias,
                         void* __restrict__ outv, int M) {
    int gt = blockIdx.x * blockDim.x + threadIdx.x;
    int node = gt >> 5, lane = gt & 31;
    if (node >= M) return;
    int e0 = g_off[node], e1 = g_off[node + 1];
    float4 a = make_float4(0.f, 0.f, 0.f, 0.f);
    for (int e = e0; e < e1; e++) {
        int s = g_csr[e];
        uint2 u = *(const uint2*)(lin + (size_t)s * 256 + lane * 4);
        float2 f0 = __half22float2(*reinterpret_cast<__half2*>(&u.x));
        float2 f1 = __half22float2(*reinterpret_cast<__half2*>(&u.y));
        a.x += f0.x; a.y += f0.y; a.z += f1.x; a.w += f1.y;
    }
    float inv = 1.0f / fmaxf((float)(e1 - e0), 1.0f);
    uint2 ru = *(const uint2*)(lin + (size_t)node * 256 + 128 + lane * 4);
    float2 r0 = __half22float2(*reinterpret_cast<__half2*>(&ru.x));
    float2 r1 = __half22float2(*reinterpret_cast<__half2*>(&ru.y));
    float4 b = *(const float4*)(bias + lane * 4);
    float4 o;
    o.x = fmaf(a.x, inv, b.x) + r0.x;
    o.y = fmaf(a.y, inv, b.y) + r0.y;
    o.z = fmaf(a.z, inv, b.z) + r1.x;
    o.w = fmaf(a.w, inv, b.w) + r1.y;
    if (OUTHALF) {
        o.x = fmaxf(o.x, 0.f); o.y = fmaxf(o.y, 0.f);
        o.z = fmaxf(o.z, 0.f); o.w = fmaxf(o.w, 0.f);
        *(uint2*)((__half*)outv + (size_t)node * 128 + lane * 4) = f4_to_h4(o);
    } else {
        *(float4*)((float*)outv + (size_t)node * 128 + lane * 4) = o;
    }
}

// ---------------- fp16 GEMM: C[M,256] = A[M,K] @ W^T (W = [256,K]) ---------
// block tile 128x128 (grid.x=2 col-blocks adjacent: A L2 reuse), BK=64,
// 8 warps (4x2), warp tile 32x64, m16n8k16 fp32-accum, fp16 C.
// Double-buffered (dynamic smem); prefetch kt+1 streams LDG->STS into the
// buffer released by the barrier at end of kt-1 => ONE barrier per K-slice.
static constexpr int GEMM_BUF = 128 * 72 * 2;          // 18432 B per tile buf
static constexpr int GEMM_SMEM = 4 * GEMM_BUF;          // A[2] + B[2] = 73728 B

template <int AHALF>
__global__ __launch_bounds__(256, 2) void gemm_fp16_k(
    const void* __restrict__ Av, const __half* __restrict__ W,
    __half* __restrict__ C, int M, int K)
{
    const float* A32 = (const float*)Av;
    const __half* A16 = (const __half*)Av;

    extern __shared__ __align__(16) char smem[];
    // layout: As buf0 | As buf1 | Bs buf0 | Bs buf1, each 128 rows x 72 halfs
    __half (*As)[72] = (__half(*)[72])smem;                       // rows 0..255
    __half (*Bs)[72] = (__half(*)[72])(smem + 2 * GEMM_BUF);      // rows 0..255

    const int tid = threadIdx.x;
    const int warp = tid >> 5, lane = tid & 31;
    const int wm = warp >> 1, wn = warp & 1;
    const int g = lane >> 2, tg = lane & 3;
    const int colBlock = blockIdx.x * 128;
    const int rowBlock = blockIdx.y * 128;

    float acc[2][8][4];
#pragma unroll
    for (int i = 0; i < 2; i++)
#pragma unroll
        for (int j = 0; j < 8; j++)
#pragma unroll
            for (int k = 0; k < 4; k++) acc[i][j][k] = 0.f;

    const int NT = K >> 6;

    const uint32_t asb = smem_u32(&As[0][0]);
    const uint32_t bsb = smem_u32(&Bs[0][0]);
    // A frags m8n8.x4 b16: lanes 0-7 rows0-7/k0-7, 8-15 rows8-15/k0-7,
    // 16-23 rows0-7/k8-15, 24-31 rows8-15/k8-15.
    const uint32_t aoff = ((wm * 32 + (lane & 15)) * 72 + (lane >> 4) * 8) * 2;
    // B frags: n-rows via lanes, k-halves via (lane>>3)&1.
    const uint32_t boff = ((wn * 64 + ((lane >> 4) * 8) + (lane & 7)) * 72
                           + ((lane >> 3) & 1) * 8) * 2;

    // stage one K-slice (64 cols) into buffer `buf`
    auto stage = [&](int buf, int k0) {
#pragma unroll
        for (int i = 0; i < 8; i++) {
            int u = tid + (i << 8);            // 2048 units: 128 rows x 16 q
            int row = u >> 4, q = u & 15;
            int gr = rowBlock + row;
            uint2 h;
            if (AHALF) {
                h = make_uint2(0u, 0u);
                if (gr < M) h = *(const uint2*)(A16 + (size_t)gr * K + k0 + q * 4);
            } else {
                float4 v = make_float4(0.f, 0.f, 0.f, 0.f);
                if (gr < M) v = *(const float4*)(A32 + (size_t)gr * K + k0 + q * 4);
                h = f4_to_h4(v);
            }
            *(uint2*)(&As[(buf << 7) + row][q * 4]) = h;
        }
#pragma unroll
        for (int i = 0; i < 8; i++) {
            int u = tid + (i << 8);
            int row = u >> 4, q = u & 15;
            *(uint2*)(&Bs[(buf << 7) + row][q * 4]) =
                *(const uint2*)(W + (size_t)(colBlock + row) * K + k0 + q * 4);
        }
    };

    stage(0, 0);
    __syncthreads();

    for (int kt = 0; kt < NT; kt++) {
        const int cur = kt & 1;
        // prefetch next slice into the buffer released by last barrier
        if (kt + 1 < NT) stage(cur ^ 1, (kt + 1) << 6);

        const uint32_t abase = asb + cur * 18432;
        const uint32_t bbase = bsb + cur * 18432;
#pragma unroll
        for (int ks = 0; ks < 4; ks++) {
            unsigned a[2][4];
#pragma unroll
            for (int mt = 0; mt < 2; mt++) {
                uint32_t addr = abase + aoff + mt * 2304 + ks * 32;
                asm volatile(
                    "ldmatrix.sync.aligned.m8n8.x4.shared.b16 {%0,%1,%2,%3}, [%4];"
                    : "=r"(a[mt][0]), "=r"(a[mt][1]), "=r"(a[mt][2]), "=r"(a[mt][3])
                    : "r"(addr));
            }
            unsigned b[8][2];
#pragma unroll
            for (int p = 0; p < 4; p++) {
                uint32_t addr = bbase + boff + p * 2304 + ks * 32;
                asm volatile(
                    "ldmatrix.sync.aligned.m8n8.x4.shared.b16 {%0,%1,%2,%3}, [%4];"
                    : "=r"(b[2 * p][0]), "=r"(b[2 * p][1]),
                      "=r"(b[2 * p + 1][0]), "=r"(b[2 * p + 1][1])
                    : "r"(addr));
            }
#pragma unroll
            for (int mt = 0; mt < 2; mt++)
#pragma unroll
                for (int nt = 0; nt < 8; nt++) {
                    asm volatile(
                        "mma.sync.aligned.m16n8k16.row.col.f32.f16.f16.f32 "
                        "{%0,%1,%2,%3}, {%4,%5,%6,%7}, {%8,%9}, {%0,%1,%2,%3};\n"
                        : "+f"(acc[mt][nt][0]), "+f"(acc[mt][nt][1]),
                          "+f"(acc[mt][nt][2]), "+f"(acc[mt][nt][3])
                        : "r"(a[mt][0]), "r"(a[mt][1]), "r"(a[mt][2]), "r"(a[mt][3]),
                          "r"(b[nt][0]), "r"(b[nt][1]));
                }
        }
        __syncthreads();   // one barrier: fences cur reads + nb writes
    }

    // epilogue, fp16 C (m16n8: c0,c1 row g; c2,c3 row g+8; cols tg*2,+1)
#pragma unroll
    for (int mt = 0; mt < 2; mt++)
#pragma unroll
        for (int nt = 0; nt < 8; nt++) {
            int row0 = rowBlock + wm * 32 + mt * 16 + g;
            int col  = colBlock + wn * 64 + nt * 8 + tg * 2;
            if (row0 < M)
                *(__half2*)(C + (size_t)row0 * 256 + col) =
                    __floats2half2_rn(acc[mt][nt][0], acc[mt][nt][1]);
            int row1 = row0 + 8;
            if (row1 < M)
                *(__half2*)(C + (size_t)row1 * 256 + col) =
                    __floats2half2_rn(acc[mt][nt][2], acc[mt][nt][3]);
        }
}

// ---------------------------------------------------------------------------
extern "C" void kernel_launch(void* const* d_in, const int* in_sizes, int n_in,
                              void* d_out, int out_size) {
    const float* x   = (const float*)d_in[0];
    const void*  ei  = d_in[1];
    const float* W1l = (const float*)d_in[2];
    const float* b1  = (const float*)d_in[3];
    const float* W1r = (const float*)d_in[4];
    const float* W2l = (const float*)d_in[5];
    const float* b2  = (const float*)d_in[6];
    const float* W2r = (const float*)d_in[7];
    float* out = (float*)d_out;

    const int M = in_sizes[0] / 384;
    const int E = in_sizes[1] / 2;
    const int NB = (M + 1023) / 1024;

    __half *pLin, *pH1, *pW1, *pW2;
    int *pDeg;
    cudaGetSymbolAddress((void**)&pLin, g_lin);
    cudaGetSymbolAddress((void**)&pH1, g_h1);
    cudaGetSymbolAddress((void**)&pW1, g_W1);
    cudaGetSymbolAddress((void**)&pW2, g_W2);
    cudaGetSymbolAddress((void**)&pDeg, g_deg);

    cudaFuncSetAttribute(gemm_fp16_k<0>, cudaFuncAttributeMaxDynamicSharedMemorySize, GEMM_SMEM);
    cudaFuncSetAttribute(gemm_fp16_k<1>, cudaFuncAttributeMaxDynamicSharedMemorySize, GEMM_SMEM);

    const int T = 256;

    // setup: edges -> CSR (4 nodes), weights -> fp16 (1 node)
    cudaMemsetAsync(pDeg, 0, (size_t)M * sizeof(int));
    prep_edges_k<<<(E + T - 1) / T, T>>>(ei, E);
    scan_k<<<NB, T>>>(M, E);
    fill_k<<<(E + T - 1) / T, T>>>(E);
    pack_all_k<<<(256 * 384 + 256 * 128 + T - 1) / T, T>>>(W1l, W1r, W2l, W2r);

    dim3 gg(2, (M + 127) / 128);
    const int gatherBlocks = (M * 32 + T - 1) / T;

    // ---- layer 1 ----
    gemm_fp16_k<0><<<gg, T, GEMM_SMEM>>>(x, pW1, pLin, M, 384);
    gather_k<1><<<gatherBlocks, T>>>(pLin, b1, pH1, M);

    // ---- layer 2 ----
    gemm_fp16_k<1><<<gg, T, GEMM_SMEM>>>(pH1, pW2, pLin, M, 128);
    gather_k<0><<<gatherBlocks, T>>>(pLin, b2, out, M);
}

// round 14
// speedup vs baseline: 2.0630x; 1.0091x over previous
#include <cuda_runtime.h>
#include <cuda_fp16.h>
#include <cstdint>
#include <cstddef>

// ---------------------------------------------------------------------------
// GraphSAGE 2-layer, GB300 sm_103a (base-PTX target: no tcgen05 available).
//   h1 = relu( segmean(x@W1l) + b1 + x@W1r )
//   out =      segmean(h1@W2l) + b2 + h1@W2r
// GEMMs fused as [K,256] = [W_l | W_r]; aggregation in projected 128-d space.
// GEMM: fp16 mma.sync.m16n8k16 (fp32 accum), BK=64, ONE barrier per K-slice,
//       at the HMMA issue floor (~4.8M mma instrs). CSR fill fused into the
//       GEMM1 launch (first blocks). Setup: 2 kernels, deg self-clearing scan.
// Gather: half-warp split (2 edges in flight, uint4 rows) + fused epilogue.
// ---------------------------------------------------------------------------

#define MAXN 100000
#define MAXE 200000

// scratch (static device globals: allocation-free contract)
__device__ __half g_W1[256 * 384];            // n-major [256][384]
__device__ __half g_W2[256 * 128];            // n-major [256][128]
__device__ __half g_lin[(size_t)MAXN * 256];
__device__ __half g_h1 [(size_t)MAXN * 128];
__device__ int    g_src[MAXE];
__device__ int    g_dst[MAXE];
__device__ int    g_deg[MAXN];                // zeroed by scan_k after use
__device__ int    g_off[MAXN + 1];
__device__ int    g_cur[MAXN];
__device__ int    g_csr[MAXE];
__device__ int    g_look[128];                // lookback slots: agg+1, 0=not ready

__device__ __forceinline__ uint32_t smem_u32(const void* p) {
    uint32_t a;
    asm("{ .reg .u64 t; cvta.to.shared.u64 t, %1; cvt.u32.u64 %0, t; }"
        : "=r"(a) : "l"(p));
    return a;
}

__device__ __forceinline__ uint2 f4_to_h4(float4 v) {
    __half2 lo = __floats2half2_rn(v.x, v.y);
    __half2 hi = __floats2half2_rn(v.z, v.w);
    uint2 r;
    r.x = *reinterpret_cast<unsigned*>(&lo);
    r.y = *reinterpret_cast<unsigned*>(&hi);
    return r;
}

// ---------------- setup: edges (detect+normalize+degree) + weight pack -----
// blocks [0, PB): edge prep; blocks [PB, ...): fp16 n-major weight pack.
__global__ void setup_k(const void* __restrict__ ei, int E,
                        const float* __restrict__ W1l, const float* __restrict__ W1r,
                        const float* __restrict__ W2l, const float* __restrict__ W2r,
                        int PB) {
    if (blockIdx.x < PB) {
        __shared__ int s_bad;
        if (threadIdx.x == 0) s_bad = 0;
        __syncthreads();
        // int64 edges (nonneg, < 2^31) => all high words of first 64 entries 0
        const unsigned* w = (const unsigned*)ei;
        if (threadIdx.x < 64 && w[2 * threadIdx.x + 1] != 0u) s_bad = 1;
        __syncthreads();
        const int is64 = !s_bad;

        int gt = blockIdx.x * blockDim.x + threadIdx.x;
        if (gt < 128) g_look[gt] = 0;          // reset lookback slots each replay
        if (gt >= E) return;
        int s, d;
        if (is64) {
            const long long* p = (const long long*)ei;
            s = (int)p[gt];
            d = (int)p[E + gt];
        } else {
            const int* p = (const int*)ei;
            s = p[gt];
            d = p[E + gt];
        }
        g_src[gt] = s;
        g_dst[gt] = d;
        atomicAdd(g_deg + d, 1);
    } else {
        int idx = (blockIdx.x - PB) * blockDim.x + threadIdx.x;
        if (idx < 256 * 384) {
            int n = idx / 384, k = idx - n * 384;
            float v = (n < 128) ? W1l[k * 128 + n] : W1r[k * 128 + n - 128];
            g_W1[idx] = __float2half_rn(v);
        } else if (idx < 256 * 384 + 256 * 128) {
            int j = idx - 256 * 384;
            int n = j >> 7, k = j & 127;
            float v = (n < 128) ? W2l[k * 128 + n] : W2r[k * 128 + n - 128];
            g_W2[j] = __float2half_rn(v);
        }
    }
}

// ---------------- CSR offsets: single-pass windowed-lookback scan ----------
// 1024 nodes per block; all blocks resident (NB<=98 < 148 SMs): spin is safe.
// Self-clears g_deg after reading (restores zeroed state for next replay).
__global__ void scan_k(int M, int E) {
    __shared__ int wsum[8];
    __shared__ int sprefix;
    const int tid = threadIdx.x, lane = tid & 31, wid = tid >> 5;
    const int b = blockIdx.x;
    const int base = b * 1024 + tid * 4;

    int d[4], sum4 = 0;
#pragma unroll
    for (int i = 0; i < 4; i++) {
        int n = base + i;
        d[i] = (n < M) ? g_deg[n] : 0;
        sum4 += d[i];
    }
    // warp inclusive scan of per-thread sums
    int t = sum4;
#pragma unroll
    for (int o = 1; o < 32; o <<= 1) {
        int v = __shfl_up_sync(0xFFFFFFFFu, t, o);
        if (lane >= o) t += v;
    }
    if (lane == 31) wsum[wid] = t;
    __syncthreads();
    if (tid < 8) {
        int wv = wsum[tid];
#pragma unroll
        for (int o = 1; o < 8; o <<= 1) {
            int v = __shfl_up_sync(0xFFu, wv, o);
            if (tid >= o) wv += v;
        }
        wsum[tid] = wv;                    // inclusive warp prefix
    }
    __syncthreads();

    // publish block aggregate (value+1, single word: no fence needed)
    if (tid == 0) *((volatile int*)&g_look[b]) = wsum[7] + 1;

    // windowed lookback: warp 0 sums all predecessor aggregates in parallel
    if (wid == 0) {
        int pre = 0;
        for (int s0 = 0; s0 < b; s0 += 32) {
            int i = s0 + lane, v = 0;
            if (i < b) {
                volatile int* p = &g_look[i];
                do { v = *p; } while (v == 0);
                v -= 1;
            }
            pre += v;
        }
#pragma unroll
        for (int o = 16; o > 0; o >>= 1) pre += __shfl_xor_sync(0xFFFFFFFFu, pre, o);
        if (lane == 0) sprefix = pre;
    }
    __syncthreads();

    int run = sprefix + (t - sum4) + (wid > 0 ? wsum[wid - 1] : 0);
#pragma unroll
    for (int i = 0; i < 4; i++) {
        int n = base + i;
        if (n < M) { g_off[n] = run; g_cur[n] = run; g_deg[n] = 0; run += d[i]; }
    }
    if (b == 0 && tid == 0) g_off[M] = E;
}

// ---------------- fused gather: mean + bias + root (+relu) -----------------
// one warp per node; half-warps process even/odd edges (uint4 = 16B/lane,
// 2 edges in flight), combined via shfl_down(16).
template <int OUTHALF>
__global__ void gather_k(const __half* __restrict__ lin, const float* __restrict__ bias,
                         void* __restrict__ outv, int M) {
    int gt = blockIdx.x * blockDim.x + threadIdx.x;
    int node = gt >> 5, lane = gt & 31;
    if (node >= M) return;
    const int half = lane >> 4, hl = lane & 15;
    int e0 = g_off[node], e1 = g_off[node + 1];

    float a[8] = {0.f, 0.f, 0.f, 0.f, 0.f, 0.f, 0.f, 0.f};
    for (int e = e0 + half; e < e1; e += 2) {
        int s = g_csr[e];
        uint4 u = *(const uint4*)(lin + (size_t)s * 256 + hl * 8);
        const __half2* h = (const __half2*)&u;
#pragma unroll
        for (int i = 0; i < 4; i++) {
            float2 f = __half22float2(h[i]);
            a[2 * i] += f.x;
            a[2 * i + 1] += f.y;
        }
    }
#pragma unroll
    for (int i = 0; i < 8; i++)
        a[i] += __shfl_down_sync(0xFFFFFFFFu, a[i], 16);

    if (half == 0) {
        float inv = 1.0f / fmaxf((float)(e1 - e0), 1.0f);
        uint4 ru = *(const uint4*)(lin + (size_t)node * 256 + 128 + hl * 8);
        const __half2* rh = (const __half2*)&ru;
        float4 b0 = *(const float4*)(bias + hl * 8);
        float4 b1 = *(const float4*)(bias + hl * 8 + 4);
        const float bb[8] = {b0.x, b0.y, b0.z, b0.w, b1.x, b1.y, b1.z, b1.w};
        float o[8];
#pragma unroll
        for (int i = 0; i < 4; i++) {
            float2 rf = __half22float2(rh[i]);
            o[2 * i]     = fmaf(a[2 * i],     inv, bb[2 * i])     + rf.x;
            o[2 * i + 1] = fmaf(a[2 * i + 1], inv, bb[2 * i + 1]) + rf.y;
        }
        if (OUTHALF) {
            uint4 w;
            unsigned* wp = (unsigned*)&w;
#pragma unroll
            for (int i = 0; i < 4; i++) {
                __half2 hh = __floats2half2_rn(fmaxf(o[2 * i], 0.f),
                                               fmaxf(o[2 * i + 1], 0.f));
                wp[i] = *reinterpret_cast<unsigned*>(&hh);
            }
            *(uint4*)((__half*)outv + (size_t)node * 128 + hl * 8) = w;
        } else {
            float* dst = (float*)outv + (size_t)node * 128 + hl * 8;
            *(float4*)dst       = make_float4(o[0], o[1], o[2], o[3]);
            *(float4*)(dst + 4) = make_float4(o[4], o[5], o[6], o[7]);
        }
    }
}

// ---------------- fp16 GEMM: C[M,256] = A[M,K] @ W^T (W = [256,K]) ---------
// 1-D grid: first nFill blocks do the CSR bucket fill (hidden under the GEMM
// ramp; gather1 already waits for this kernel), rest are GEMM tiles.
// Block tile 128x128 (col-blocks adjacent: A L2 reuse), BK=64, 8 warps (4x2),
// warp tile 32x64, m16n8k16 fp32-accum, ONE barrier per K-slice, fp16 C.
static constexpr int GEMM_BUF = 128 * 72 * 2;          // 18432 B per tile buf
static constexpr int GEMM_SMEM = 4 * GEMM_BUF;          // A[2] + B[2] = 73728 B

template <int AHALF>
__global__ __launch_bounds__(256, 2) void gemm_fp16_k(
    const void* __restrict__ Av, const __half* __restrict__ W,
    __half* __restrict__ C, int M, int K, int nFill, int E)
{
    const int tid = threadIdx.x;
    if ((int)blockIdx.x < nFill) {          // fused CSR fill
        int e = blockIdx.x * 256 + tid;
        if (e < E) {
            int pos = atomicAdd(g_cur + g_dst[e], 1);
            g_csr[pos] = g_src[e];
        }
        return;
    }
    const int bid = blockIdx.x - nFill;

    const float* A32 = (const float*)Av;
    const __half* A16 = (const __half*)Av;

    extern __shared__ __align__(16) char smem[];
    __half (*As)[72] = (__half(*)[72])smem;
    __half (*Bs)[72] = (__half(*)[72])(smem + 2 * GEMM_BUF);

    const int warp = tid >> 5, lane = tid & 31;
    const int wm = warp >> 1, wn = warp & 1;
    const int g = lane >> 2, tg = lane & 3;
    const int colBlock = (bid & 1) * 128;   // col-blocks adjacent: A L2 reuse
    const int rowBlock = (bid >> 1) * 128;

    float acc[2][8][4];
#pragma unroll
    for (int i = 0; i < 2; i++)
#pragma unroll
        for (int j = 0; j < 8; j++)
#pragma unroll
            for (int k = 0; k < 4; k++) acc[i][j][k] = 0.f;

    const int NT = K >> 6;

    const uint32_t asb = smem_u32(&As[0][0]);
    const uint32_t bsb = smem_u32(&Bs[0][0]);
    const uint32_t aoff = ((wm * 32 + (lane & 15)) * 72 + (lane >> 4) * 8) * 2;
    const uint32_t boff = ((wn * 64 + ((lane >> 4) * 8) + (lane & 7)) * 72
                           + ((lane >> 3) & 1) * 8) * 2;

    auto stage = [&](int buf, int k0) {
#pragma unroll
        for (int i = 0; i < 8; i++) {
            int u = tid + (i << 8);
            int row = u >> 4, q = u & 15;
            int gr = rowBlock + row;
            uint2 h;
            if (AHALF) {
                h = make_uint2(0u, 0u);
                if (gr < M) h = *(const uint2*)(A16 + (size_t)gr * K + k0 + q * 4);
            } else {
                float4 v = make_float4(0.f, 0.f, 0.f, 0.f);
                if (gr < M) v = *(const float4*)(A32 + (size_t)gr * K + k0 + q * 4);
                h = f4_to_h4(v);
            }
            *(uint2*)(&As[(buf << 7) + row][q * 4]) = h;
        }
#pragma unroll
        for (int i = 0; i < 8; i++) {
            int u = tid + (i << 8);
            int row = u >> 4, q = u & 15;
            *(uint2*)(&Bs[(buf << 7) + row][q * 4]) =
                *(const uint2*)(W + (size_t)(colBlock + row) * K + k0 + q * 4);
        }
    };

    stage(0, 0);
    __syncthreads();

    for (int kt = 0; kt < NT; kt++) {
        const int cur = kt & 1;
        if (kt + 1 < NT) stage(cur ^ 1, (kt + 1) << 6);

        const uint32_t abase = asb + cur * 18432;
        const uint32_t bbase = bsb + cur * 18432;
#pragma unroll
        for (int ks = 0; ks < 4; ks++) {
            unsigned a[2][4];
#pragma unroll
            for (int mt = 0; mt < 2; mt++) {
                uint32_t addr = abase + aoff + mt * 2304 + ks * 32;
                asm volatile(
                    "ldmatrix.sync.aligned.m8n8.x4.shared.b16 {%0,%1,%2,%3}, [%4];"
                    : "=r"(a[mt][0]), "=r"(a[mt][1]), "=r"(a[mt][2]), "=r"(a[mt][3])
                    : "r"(addr));
            }
            unsigned b[8][2];
#pragma unroll
            for (int p = 0; p < 4; p++) {
                uint32_t addr = bbase + boff + p * 2304 + ks * 32;
                asm volatile(
                    "ldmatrix.sync.aligned.m8n8.x4.shared.b16 {%0,%1,%2,%3}, [%4];"
                    : "=r"(b[2 * p][0]), "=r"(b[2 * p][1]),
                      "=r"(b[2 * p + 1][0]), "=r"(b[2 * p + 1][1])
                    : "r"(addr));
            }
#pragma unroll
            for (int mt = 0; mt < 2; mt++)
#pragma unroll
                for (int nt = 0; nt < 8; nt++) {
                    asm volatile(
                        "mma.sync.aligned.m16n8k16.row.col.f32.f16.f16.f32 "
                        "{%0,%1,%2,%3}, {%4,%5,%6,%7}, {%8,%9}, {%0,%1,%2,%3};\n"
                        : "+f"(acc[mt][nt][0]), "+f"(acc[mt][nt][1]),
                          "+f"(acc[mt][nt][2]), "+f"(acc[mt][nt][3])
                        : "r"(a[mt][0]), "r"(a[mt][1]), "r"(a[mt][2]), "r"(a[mt][3]),
                          "r"(b[nt][0]), "r"(b[nt][1]));
                }
        }
        __syncthreads();   // one barrier: fences cur reads + next-buf writes
    }

    // epilogue, fp16 C (m16n8: c0,c1 row g; c2,c3 row g+8; cols tg*2,+1)
#pragma unroll
    for (int mt = 0; mt < 2; mt++)
#pragma unroll
        for (int nt = 0; nt < 8; nt++) {
            int row0 = rowBlock + wm * 32 + mt * 16 + g;
            int col  = colBlock + wn * 64 + nt * 8 + tg * 2;
            if (row0 < M)
                *(__half2*)(C + (size_t)row0 * 256 + col) =
                    __floats2half2_rn(acc[mt][nt][0], acc[mt][nt][1]);
            int row1 = row0 + 8;
            if (row1 < M)
                *(__half2*)(C + (size_t)row1 * 256 + col) =
                    __floats2half2_rn(acc[mt][nt][2], acc[mt][nt][3]);
        }
}

// ---------------------------------------------------------------------------
extern "C" void kernel_launch(void* const* d_in, const int* in_sizes, int n_in,
                              void* d_out, int out_size) {
    const float* x   = (const float*)d_in[0];
    const void*  ei  = d_in[1];
    const float* W1l = (const float*)d_in[2];
    const float* b1  = (const float*)d_in[3];
    const float* W1r = (const float*)d_in[4];
    const float* W2l = (const float*)d_in[5];
    const float* b2  = (const float*)d_in[6];
    const float* W2r = (const float*)d_in[7];
    float* out = (float*)d_out;

    const int M = in_sizes[0] / 384;
    const int E = in_sizes[1] / 2;
    const int NB = (M + 1023) / 1024;

    __half *pLin, *pH1, *pW1, *pW2;
    cudaGetSymbolAddress((void**)&pLin, g_lin);
    cudaGetSymbolAddress((void**)&pH1, g_h1);
    cudaGetSymbolAddress((void**)&pW1, g_W1);
    cudaGetSymbolAddress((void**)&pW2, g_W2);

    cudaFuncSetAttribute(gemm_fp16_k<0>, cudaFuncAttributeMaxDynamicSharedMemorySize, GEMM_SMEM);
    cudaFuncSetAttribute(gemm_fp16_k<1>, cudaFuncAttributeMaxDynamicSharedMemorySize, GEMM_SMEM);

    const int T = 256;
    const int PB = (E + T - 1) / T;                         // prep blocks
    const int WB = (256 * 384 + 256 * 128 + T - 1) / T;     // pack blocks
    const int RB = (M + 127) / 128;                         // gemm row blocks
    const int gatherBlocks = (M * 32 + T - 1) / T;

    // setup: [edge prep + weight pack] -> [offset scan] (deg self-clears)
    setup_k<<<PB + WB, T>>>(ei, E, W1l, W1r, W2l, W2r, PB);
    scan_k<<<NB, T>>>(M, E);

    // ---- layer 1 (CSR fill fused into GEMM1 launch) ----
    gemm_fp16_k<0><<<PB + 2 * RB, T, GEMM_SMEM>>>(x, pW1, pLin, M, 384, PB, E);
    gather_k<1><<<gatherBlocks, T>>>(pLin, b1, pH1, M);

    // ---- layer 2 ----
    gemm_fp16_k<1><<<2 * RB, T, GEMM_SMEM>>>(pH1, pW2, pLin, M, 128, 0, E);
    gather_k<0><<<gatherBlocks, T>>>(pLin, b2, out, M);
}

// round 15
// speedup vs baseline: 2.2010x; 1.0669x over previous
#include <cuda_runtime.h>
#include <cuda_fp16.h>
#include <cstdint>
#include <cstddef>

// ---------------------------------------------------------------------------
// GraphSAGE 2-layer, GB300 sm_103a (base-PTX target: no tcgen05 available).
//   h1 = relu( segmean(x@W1l) + b1 + x@W1r )
//   out =      segmean(h1@W2l) + b2 + h1@W2r
// GEMMs fused as [K,256] = [W_l | W_r]; aggregation in projected 128-d space.
// GEMM: fp16 mma.sync.m16n8k16 (fp32 accum), BK=64, ONE barrier per K-slice,
//       at the HMMA issue floor. x read with __ldcs (evict-first) so the 51MB
//       fp16 lin stays L2-resident for the gathers. CSR fill fused into GEMM1.
// Gather: warp handles 4 consecutive nodes (8x fewer CTAs), half-warp 2-edge
//       MLP, csr index prefetch, 32-bit addressing, streaming final store.
// ---------------------------------------------------------------------------

#define MAXN 100000
#define MAXE 200000

// scratch (static device globals: allocation-free contract)
__device__ __half g_W1[256 * 384];            // n-major [256][384]
__device__ __half g_W2[256 * 128];            // n-major [256][128]
__device__ __half g_lin[(size_t)MAXN * 256];
__device__ __half g_h1 [(size_t)MAXN * 128];
__device__ int    g_src[MAXE];
__device__ int    g_dst[MAXE];
__device__ int    g_deg[MAXN];                // zeroed by scan_k after use
__device__ int    g_off[MAXN + 1];
__device__ int    g_cur[MAXN];
__device__ int    g_csr[MAXE];
__device__ int    g_look[128];                // lookback slots: agg+1, 0=not ready

__device__ __forceinline__ uint32_t smem_u32(const void* p) {
    uint32_t a;
    asm("{ .reg .u64 t; cvta.to.shared.u64 t, %1; cvt.u32.u64 %0, t; }"
        : "=r"(a) : "l"(p));
    return a;
}

__device__ __forceinline__ uint2 f4_to_h4(float4 v) {
    __half2 lo = __floats2half2_rn(v.x, v.y);
    __half2 hi = __floats2half2_rn(v.z, v.w);
    uint2 r;
    r.x = *reinterpret_cast<unsigned*>(&lo);
    r.y = *reinterpret_cast<unsigned*>(&hi);
    return r;
}

// ---------------- setup: edges (detect+normalize+degree) + weight pack -----
__global__ void setup_k(const void* __restrict__ ei, int E,
                        const float* __restrict__ W1l, const float* __restrict__ W1r,
                        const float* __restrict__ W2l, const float* __restrict__ W2r,
                        int PB) {
    if (blockIdx.x < PB) {
        __shared__ int s_bad;
        if (threadIdx.x == 0) s_bad = 0;
        __syncthreads();
        // int64 edges (nonneg, < 2^31) => all high words of first 64 entries 0
        const unsigned* w = (const unsigned*)ei;
        if (threadIdx.x < 64 && w[2 * threadIdx.x + 1] != 0u) s_bad = 1;
        __syncthreads();
        const int is64 = !s_bad;

        int gt = blockIdx.x * blockDim.x + threadIdx.x;
        if (gt < 128) g_look[gt] = 0;          // reset lookback slots each replay
        if (gt >= E) return;
        int s, d;
        if (is64) {
            const long long* p = (const long long*)ei;
            s = (int)p[gt];
            d = (int)p[E + gt];
        } else {
            const int* p = (const int*)ei;
            s = p[gt];
            d = p[E + gt];
        }
        g_src[gt] = s;
        g_dst[gt] = d;
        atomicAdd(g_deg + d, 1);
    } else {
        int idx = (blockIdx.x - PB) * blockDim.x + threadIdx.x;
        if (idx < 256 * 384) {
            int n = idx / 384, k = idx - n * 384;
            float v = (n < 128) ? W1l[k * 128 + n] : W1r[k * 128 + n - 128];
            g_W1[idx] = __float2half_rn(v);
        } else if (idx < 256 * 384 + 256 * 128) {
            int j = idx - 256 * 384;
            int n = j >> 7, k = j & 127;
            float v = (n < 128) ? W2l[k * 128 + n] : W2r[k * 128 + n - 128];
            g_W2[j] = __float2half_rn(v);
        }
    }
}

// ---------------- CSR offsets: single-pass windowed-lookback scan ----------
// 1024 nodes per block; all blocks resident (NB<=98 < 148 SMs): spin is safe.
// Self-clears g_deg after reading (restores zeroed state for next replay).
__global__ void scan_k(int M, int E) {
    __shared__ int wsum[8];
    __shared__ int sprefix;
    const int tid = threadIdx.x, lane = tid & 31, wid = tid >> 5;
    const int b = blockIdx.x;
    const int base = b * 1024 + tid * 4;

    int d[4], sum4 = 0;
#pragma unroll
    for (int i = 0; i < 4; i++) {
        int n = base + i;
        d[i] = (n < M) ? g_deg[n] : 0;
        sum4 += d[i];
    }
    int t = sum4;
#pragma unroll
    for (int o = 1; o < 32; o <<= 1) {
        int v = __shfl_up_sync(0xFFFFFFFFu, t, o);
        if (lane >= o) t += v;
    }
    if (lane == 31) wsum[wid] = t;
    __syncthreads();
    if (tid < 8) {
        int wv = wsum[tid];
#pragma unroll
        for (int o = 1; o < 8; o <<= 1) {
            int v = __shfl_up_sync(0xFFu, wv, o);
            if (tid >= o) wv += v;
        }
        wsum[tid] = wv;                    // inclusive warp prefix
    }
    __syncthreads();

    if (tid == 0) *((volatile int*)&g_look[b]) = wsum[7] + 1;

    if (wid == 0) {
        int pre = 0;
        for (int s0 = 0; s0 < b; s0 += 32) {
            int i = s0 + lane, v = 0;
            if (i < b) {
                volatile int* p = &g_look[i];
                do { v = *p; } while (v == 0);
                v -= 1;
            }
            pre += v;
        }
#pragma unroll
        for (int o = 16; o > 0; o >>= 1) pre += __shfl_xor_sync(0xFFFFFFFFu, pre, o);
        if (lane == 0) sprefix = pre;
    }
    __syncthreads();

    int run = sprefix + (t - sum4) + (wid > 0 ? wsum[wid - 1] : 0);
#pragma unroll
    for (int i = 0; i < 4; i++) {
        int n = base + i;
        if (n < M) { g_off[n] = run; g_cur[n] = run; g_deg[n] = 0; run += d[i]; }
    }
    if (b == 0 && tid == 0) g_off[M] = E;
}

// ---------------- fused gather: mean + bias + root (+relu) -----------------
// warp handles NPW consecutive nodes (csr locality, 8x fewer CTAs);
// half-warps process even/odd edges (256B full-row uint4 loads, 2-edge MLP)
// with next-index prefetch; all addressing 32-bit.
#define NPW 4
template <int OUTHALF>
__global__ void gather_k(const __half* __restrict__ lin, const float* __restrict__ bias,
                         void* __restrict__ outv, int M) {
    const int warpId = (blockIdx.x * blockDim.x + threadIdx.x) >> 5;
    const int lane = threadIdx.x & 31;
    const int half = lane >> 4, hl = lane & 15;
    const unsigned hoff = hl * 8u;

    float4 b0 = *(const float4*)(bias + hl * 8);
    float4 b1 = *(const float4*)(bias + hl * 8 + 4);

    int n0 = warpId * NPW;
#pragma unroll
    for (int ni = 0; ni < NPW; ni++) {
        int node = n0 + ni;
        if (node >= M) return;
        int e0 = g_off[node], e1 = g_off[node + 1];

        float a[8] = {0.f, 0.f, 0.f, 0.f, 0.f, 0.f, 0.f, 0.f};
        int e = e0 + half;
        int s = (e < e1) ? g_csr[e] : -1;
        while (s >= 0) {
            int e2 = e + 2;
            int snext = (e2 < e1) ? g_csr[e2] : -1;   // prefetch next index
            uint4 u = *(const uint4*)(lin + ((unsigned)s << 8) + hoff);
            const __half2* h = (const __half2*)&u;
#pragma unroll
            for (int i = 0; i < 4; i++) {
                float2 f = __half22float2(h[i]);
                a[2 * i] += f.x;
                a[2 * i + 1] += f.y;
            }
            s = snext;
            e = e2;
        }
#pragma unroll
        for (int i = 0; i < 8; i++)
            a[i] += __shfl_down_sync(0xFFFFFFFFu, a[i], 16);

        if (half == 0) {
            float inv = 1.0f / fmaxf((float)(e1 - e0), 1.0f);
            uint4 ru = *(const uint4*)(lin + ((unsigned)node << 8) + 128u + hoff);
            const __half2* rh = (const __half2*)&ru;
            const float bb[8] = {b0.x, b0.y, b0.z, b0.w, b1.x, b1.y, b1.z, b1.w};
            float o[8];
#pragma unroll
            for (int i = 0; i < 4; i++) {
                float2 rf = __half22float2(rh[i]);
                o[2 * i]     = fmaf(a[2 * i],     inv, bb[2 * i])     + rf.x;
                o[2 * i + 1] = fmaf(a[2 * i + 1], inv, bb[2 * i + 1]) + rf.y;
            }
            if (OUTHALF) {
                uint4 w;
                unsigned* wp = (unsigned*)&w;
#pragma unroll
                for (int i = 0; i < 4; i++) {
                    __half2 hh = __floats2half2_rn(fmaxf(o[2 * i], 0.f),
                                                   fmaxf(o[2 * i + 1], 0.f));
                    wp[i] = *reinterpret_cast<unsigned*>(&hh);
                }
                *(uint4*)((__half*)outv + ((unsigned)node << 7) + hoff) = w;
            } else {
                float* dst = (float*)outv + ((unsigned)node << 7) + hoff;
                __stcs((float4*)dst,       make_float4(o[0], o[1], o[2], o[3]));
                __stcs((float4*)(dst + 4), make_float4(o[4], o[5], o[6], o[7]));
            }
        }
    }
}

// ---------------- fp16 GEMM: C[M,256] = A[M,K] @ W^T (W = [256,K]) ---------
// 1-D grid: first nFill blocks do the CSR bucket fill (hidden under the GEMM
// ramp), rest are GEMM tiles. Block tile 128x128 (col-blocks adjacent:
// A L2 reuse), BK=64, 8 warps (4x2), warp tile 32x64, m16n8k16 fp32-accum,
// ONE barrier per K-slice, fp16 C. fp32 A read via __ldcs (evict-first) so
// the lin output stays L2-resident for the gather.
static constexpr int GEMM_BUF = 128 * 72 * 2;          // 18432 B per tile buf
static constexpr int GEMM_SMEM = 4 * GEMM_BUF;          // A[2] + B[2] = 73728 B

template <int AHALF>
__global__ __launch_bounds__(256, 2) void gemm_fp16_k(
    const void* __restrict__ Av, const __half* __restrict__ W,
    __half* __restrict__ C, int M, int K, int nFill, int E)
{
    const int tid = threadIdx.x;
    if ((int)blockIdx.x < nFill) {          // fused CSR fill
        int e = blockIdx.x * 256 + tid;
        if (e < E) {
            int pos = atomicAdd(g_cur + g_dst[e], 1);
            g_csr[pos] = g_src[e];
        }
        return;
    }
    const int bid = blockIdx.x - nFill;

    const float* A32 = (const float*)Av;
    const __half* A16 = (const __half*)Av;

    extern __shared__ __align__(16) char smem[];
    __half (*As)[72] = (__half(*)[72])smem;
    __half (*Bs)[72] = (__half(*)[72])(smem + 2 * GEMM_BUF);

    const int warp = tid >> 5, lane = tid & 31;
    const int wm = warp >> 1, wn = warp & 1;
    const int g = lane >> 2, tg = lane & 3;
    const int colBlock = (bid & 1) * 128;   // col-blocks adjacent: A L2 reuse
    const int rowBlock = (bid >> 1) * 128;

    float acc[2][8][4];
#pragma unroll
    for (int i = 0; i < 2; i++)
#pragma unroll
        for (int j = 0; j < 8; j++)
#pragma unroll
            for (int k = 0; k < 4; k++) acc[i][j][k] = 0.f;

    const int NT = K >> 6;

    const uint32_t asb = smem_u32(&As[0][0]);
    const uint32_t bsb = smem_u32(&Bs[0][0]);
    const uint32_t aoff = ((wm * 32 + (lane & 15)) * 72 + (lane >> 4) * 8) * 2;
    const uint32_t boff = ((wn * 64 + ((lane >> 4) * 8) + (lane & 7)) * 72
                           + ((lane >> 3) & 1) * 8) * 2;

    auto stage = [&](int buf, int k0) {
#pragma unroll
        for (int i = 0; i < 8; i++) {
            int u = tid + (i << 8);
            int row = u >> 4, q = u & 15;
            int gr = rowBlock + row;
            uint2 h;
            if (AHALF) {
                h = make_uint2(0u, 0u);
                if (gr < M) h = *(const uint2*)(A16 + (size_t)gr * K + k0 + q * 4);
            } else {
                float4 v = make_float4(0.f, 0.f, 0.f, 0.f);
                if (gr < M) v = __ldcs((const float4*)(A32 + (size_t)gr * K + k0 + q * 4));
                h = f4_to_h4(v);
            }
            *(uint2*)(&As[(buf << 7) + row][q * 4]) = h;
        }
#pragma unroll
        for (int i = 0; i < 8; i++) {
            int u = tid + (i << 8);
            int row = u >> 4, q = u & 15;
            *(uint2*)(&Bs[(buf << 7) + row][q * 4]) =
                *(const uint2*)(W + (size_t)(colBlock + row) * K + k0 + q * 4);
        }
    };

    stage(0, 0);
    __syncthreads();

    for (int kt = 0; kt < NT; kt++) {
        const int cur = kt & 1;
        if (kt + 1 < NT) stage(cur ^ 1, (kt + 1) << 6);

        const uint32_t abase = asb + cur * 18432;
        const uint32_t bbase = bsb + cur * 18432;
#pragma unroll
        for (int ks = 0; ks < 4; ks++) {
            unsigned a[2][4];
#pragma unroll
            for (int mt = 0; mt < 2; mt++) {
                uint32_t addr = abase + aoff + mt * 2304 + ks * 32;
                asm volatile(
                    "ldmatrix.sync.aligned.m8n8.x4.shared.b16 {%0,%1,%2,%3}, [%4];"
                    : "=r"(a[mt][0]), "=r"(a[mt][1]), "=r"(a[mt][2]), "=r"(a[mt][3])
                    : "r"(addr));
            }
            unsigned b[8][2];
#pragma unroll
            for (int p = 0; p < 4; p++) {
                uint32_t addr = bbase + boff + p * 2304 + ks * 32;
                asm volatile(
                    "ldmatrix.sync.aligned.m8n8.x4.shared.b16 {%0,%1,%2,%3}, [%4];"
                    : "=r"(b[2 * p][0]), "=r"(b[2 * p][1]),
                      "=r"(b[2 * p + 1][0]), "=r"(b[2 * p + 1][1])
                    : "r"(addr));
            }
#pragma unroll
            for (int mt = 0; mt < 2; mt++)
#pragma unroll
                for (int nt = 0; nt < 8; nt++) {
                    asm volatile(
                        "mma.sync.aligned.m16n8k16.row.col.f32.f16.f16.f32 "
                        "{%0,%1,%2,%3}, {%4,%5,%6,%7}, {%8,%9}, {%0,%1,%2,%3};\n"
                        : "+f"(acc[mt][nt][0]), "+f"(acc[mt][nt][1]),
                          "+f"(acc[mt][nt][2]), "+f"(acc[mt][nt][3])
                        : "r"(a[mt][0]), "r"(a[mt][1]), "r"(a[mt][2]), "r"(a[mt][3]),
                          "r"(b[nt][0]), "r"(b[nt][1]));
                }
        }
        __syncthreads();   // one barrier: fences cur reads + next-buf writes
    }

    // epilogue, fp16 C (m16n8: c0,c1 row g; c2,c3 row g+8; cols tg*2,+1)
#pragma unroll
    for (int mt = 0; mt < 2; mt++)
#pragma unroll
        for (int nt = 0; nt < 8; nt++) {
            int row0 = rowBlock + wm * 32 + mt * 16 + g;
            int col  = colBlock + wn * 64 + nt * 8 + tg * 2;
            if (row0 < M)
                *(__half2*)(C + (size_t)row0 * 256 + col) =
                    __floats2half2_rn(acc[mt][nt][0], acc[mt][nt][1]);
            int row1 = row0 + 8;
            if (row1 < M)
                *(__half2*)(C + (size_t)row1 * 256 + col) =
                    __floats2half2_rn(acc[mt][nt][2], acc[mt][nt][3]);
        }
}

// ---------------------------------------------------------------------------
extern "C" void kernel_launch(void* const* d_in, const int* in_sizes, int n_in,
                              void* d_out, int out_size) {
    const float* x   = (const float*)d_in[0];
    const void*  ei  = d_in[1];
    const float* W1l = (const float*)d_in[2];
    const float* b1  = (const float*)d_in[3];
    const float* W1r = (const float*)d_in[4];
    const float* W2l = (const float*)d_in[5];
    const float* b2  = (const float*)d_in[6];
    const float* W2r = (const float*)d_in[7];
    float* out = (float*)d_out;

    const int M = in_sizes[0] / 384;
    const int E = in_sizes[1] / 2;
    const int NB = (M + 1023) / 1024;

    __half *pLin, *pH1, *pW1, *pW2;
    cudaGetSymbolAddress((void**)&pLin, g_lin);
    cudaGetSymbolAddress((void**)&pH1, g_h1);
    cudaGetSymbolAddress((void**)&pW1, g_W1);
    cudaGetSymbolAddress((void**)&pW2, g_W2);

    cudaFuncSetAttribute(gemm_fp16_k<0>, cudaFuncAttributeMaxDynamicSharedMemorySize, GEMM_SMEM);
    cudaFuncSetAttribute(gemm_fp16_k<1>, cudaFuncAttributeMaxDynamicSharedMemorySize, GEMM_SMEM);

    const int T = 256;
    const int PB = (E + T - 1) / T;                         // prep blocks
    const int WB = (256 * 384 + 256 * 128 + T - 1) / T;     // pack blocks
    const int RB = (M + 127) / 128;                         // gemm row blocks
    const int gatherBlocks = (M + NPW * 8 - 1) / (NPW * 8); // warp = NPW nodes

    // setup: [edge prep + weight pack] -> [offset scan] (deg self-clears)
    setup_k<<<PB + WB, T>>>(ei, E, W1l, W1r, W2l, W2r, PB);
    scan_k<<<NB, T>>>(M, E);

    // ---- layer 1 (CSR fill fused into GEMM1 launch) ----
    gemm_fp16_k<0><<<PB + 2 * RB, T, GEMM_SMEM>>>(x, pW1, pLin, M, 384, PB, E);
    gather_k<1><<<gatherBlocks, T>>>(pLin, b1, pH1, M);

    // ---- layer 2 ----
    gemm_fp16_k<1><<<2 * RB, T, GEMM_SMEM>>>(pH1, pW2, pLin, M, 128, 0, E);
    gather_k<0><<<gatherBlocks, T>>>(pLin, b2, out, M);
}